// round 1
// baseline (speedup 1.0000x reference)
#include <cuda_runtime.h>
#include <cuda_bf16.h>
#include <cstdint>
#include <cstddef>

// Problem constants
#define Bb 2
#define Ss 2048
#define Dd 1024
#define Hh 16
#define HD 64
#define Mm 4096
#define NTOK (Bb*Ss)          // 4096
#define FOURD (4*Dd)          // 4096
#define EPS 1e-5f

// ---------------- scratch (static device globals; no allocation) -------------
__device__ float g_h[(size_t)NTOK * FOURD];   // silu(x@w1^T+b1)   64 MB
__device__ float g_y[(size_t)NTOK * Dd];      // gated attention out 16 MB
__device__ float g_z[(size_t)NTOK * Dd];      // LN1 out            16 MB
__device__ float g_t[(size_t)NTOK * Dd];      // GEMM2 out          16 MB

// ---------------- GEMM: C = [silu](A @ W^T + bias) ---------------------------
// A: [Mrows,K] row-major, W: [N,K] row-major (so both K-contiguous), C: [Mrows,N]
#define BM 128
#define BN 128
#define BK 16

template<bool SILU>
__global__ __launch_bounds__(256)
void gemm_bias_kernel(const float* __restrict__ A, const float* __restrict__ W,
                      const float* __restrict__ bias, float* __restrict__ C,
                      int Mrows, int N, int K) {
    __shared__ float As[BK][BM + 4];
    __shared__ float Bs[BK][BN + 4];
    const int m0 = blockIdx.y * BM;
    const int n0 = blockIdx.x * BN;
    const int tid = threadIdx.x;
    const int tx = tid & 15;   // 0..15  -> N
    const int ty = tid >> 4;   // 0..15  -> M

    float acc[8][8];
    #pragma unroll
    for (int i = 0; i < 8; i++)
        #pragma unroll
        for (int j = 0; j < 8; j++) acc[i][j] = 0.f;

    for (int k0 = 0; k0 < K; k0 += BK) {
        // load A tile (128x16) transposed into As[k][m]
        #pragma unroll
        for (int it = 0; it < 2; it++) {
            int idx = it * 256 + tid;        // 0..511 float4 units
            int r = idx >> 2;                // 0..127
            int c4 = idx & 3;                // 0..3
            float4 g = *(const float4*)&A[(size_t)(m0 + r) * K + k0 + c4 * 4];
            As[c4*4+0][r] = g.x; As[c4*4+1][r] = g.y;
            As[c4*4+2][r] = g.z; As[c4*4+3][r] = g.w;
        }
        // load W tile (128x16) transposed into Bs[k][n]
        #pragma unroll
        for (int it = 0; it < 2; it++) {
            int idx = it * 256 + tid;
            int r = idx >> 2;
            int c4 = idx & 3;
            float4 g = *(const float4*)&W[(size_t)(n0 + r) * K + k0 + c4 * 4];
            Bs[c4*4+0][r] = g.x; Bs[c4*4+1][r] = g.y;
            Bs[c4*4+2][r] = g.z; Bs[c4*4+3][r] = g.w;
        }
        __syncthreads();
        #pragma unroll
        for (int k = 0; k < BK; k++) {
            float a[8], b[8];
            *(float4*)&a[0] = *(const float4*)&As[k][ty*8 + 0];
            *(float4*)&a[4] = *(const float4*)&As[k][ty*8 + 4];
            *(float4*)&b[0] = *(const float4*)&Bs[k][tx*8 + 0];
            *(float4*)&b[4] = *(const float4*)&Bs[k][tx*8 + 4];
            #pragma unroll
            for (int i = 0; i < 8; i++)
                #pragma unroll
                for (int j = 0; j < 8; j++)
                    acc[i][j] = fmaf(a[i], b[j], acc[i][j]);
        }
        __syncthreads();
    }
    #pragma unroll
    for (int i = 0; i < 8; i++) {
        const int m = m0 + ty*8 + i;
        #pragma unroll
        for (int j = 0; j < 8; j++) {
            const int n = n0 + tx*8 + j;
            float v = acc[i][j] + bias[n];
            if (SILU) v = v / (1.f + __expf(-v));
            C[(size_t)m * N + n] = v;
        }
    }
}

// ---------------- fused causal silu-attention + u-gate -----------------------
// y[b,s,h*64+d] = u[b,s,h,d] * sum_k silu(q.k + bias(k-q)) [k<=q] * v[b,k,h,d]
// q,k,v,u live in g_h slices. One CTA = 64 query rows of one (b,h).
#define QT 64
#define PADW 68

__global__ __launch_bounds__(256)
void attn_kernel(const float* __restrict__ pos_w, float* __restrict__ y) {
    extern __shared__ float sm[];
    float (*Qs)[PADW] = (float(*)[PADW])sm;                    // Qs[d][q]
    float (*Ks)[PADW] = (float(*)[PADW])(sm + 64*PADW);        // Ks[d][k]
    float (*Vs)[PADW] = (float(*)[PADW])(sm + 2*64*PADW);      // Vs[k][d]
    float (*Ps)[PADW] = (float(*)[PADW])(sm + 3*64*PADW);      // Ps[k][q]

    const int qt   = blockIdx.x;
    const int head = blockIdx.y;
    const int b    = blockIdx.z;
    const int tid  = threadIdx.x;
    const int tx = tid & 15, ty = tid >> 4;
    const int q0 = ty * 4, d0 = tx * 4;

    const size_t rs = FOURD;
    const float* ubase = g_h + (size_t)b * Ss * rs + 0*Dd + head * HD;
    const float* qbase = g_h + (size_t)b * Ss * rs + 1*Dd + head * HD;
    const float* kbase = g_h + (size_t)b * Ss * rs + 2*Dd + head * HD;
    const float* vbase = g_h + (size_t)b * Ss * rs + 3*Dd + head * HD;

    // load Q tile transposed
    #pragma unroll
    for (int it = 0; it < 4; it++) {
        int idx = it * 256 + tid;     // 0..1023 float4 units
        int r = idx >> 4;             // local q row 0..63
        int c4 = idx & 15;            // 0..15
        float4 g = *(const float4*)&qbase[(size_t)(qt*QT + r) * rs + c4*4];
        Qs[c4*4+0][r] = g.x; Qs[c4*4+1][r] = g.y;
        Qs[c4*4+2][r] = g.z; Qs[c4*4+3][r] = g.w;
    }

    float o[4][4];
    #pragma unroll
    for (int i = 0; i < 4; i++)
        #pragma unroll
        for (int j = 0; j < 4; j++) o[i][j] = 0.f;

    for (int jt = 0; jt <= qt; jt++) {
        // load K tile (transposed) and V tile (direct)
        #pragma unroll
        for (int it = 0; it < 4; it++) {
            int idx = it * 256 + tid;
            int r = idx >> 4;
            int c4 = idx & 15;
            float4 gk = *(const float4*)&kbase[(size_t)(jt*QT + r) * rs + c4*4];
            Ks[c4*4+0][r] = gk.x; Ks[c4*4+1][r] = gk.y;
            Ks[c4*4+2][r] = gk.z; Ks[c4*4+3][r] = gk.w;
            float4 gv = *(const float4*)&vbase[(size_t)(jt*QT + r) * rs + c4*4];
            *(float4*)&Vs[r][c4*4] = gv;
        }
        __syncthreads();

        // S = Q @ K^T (64x64, 4x4 per thread)
        float s[4][4];
        #pragma unroll
        for (int i = 0; i < 4; i++)
            #pragma unroll
            for (int j = 0; j < 4; j++) s[i][j] = 0.f;
        #pragma unroll 8
        for (int d = 0; d < 64; d++) {
            float a[4], bb[4];
            #pragma unroll
            for (int i = 0; i < 4; i++) a[i]  = Qs[d][q0 + i];
            #pragma unroll
            for (int j = 0; j < 4; j++) bb[j] = Ks[d][tx*4 + j];
            #pragma unroll
            for (int i = 0; i < 4; i++)
                #pragma unroll
                for (int j = 0; j < 4; j++)
                    s[i][j] = fmaf(a[i], bb[j], s[i][j]);
        }
        // bias + silu + causal mask; write P transposed: Ps[k][q]
        #pragma unroll
        for (int i = 0; i < 4; i++) {
            const int gq = qt*QT + q0 + i;
            #pragma unroll
            for (int j = 0; j < 4; j++) {
                const int gk = jt*QT + tx*4 + j;
                float v = s[i][j] + pos_w[Mm - 1 + gk - gq];
                v = v / (1.f + __expf(-v));
                if (gk > gq) v = 0.f;
                Ps[tx*4 + j][q0 + i] = v;
            }
        }
        __syncthreads();

        // O += P @ V
        #pragma unroll 8
        for (int k = 0; k < 64; k++) {
            float p[4], vv[4];
            #pragma unroll
            for (int i = 0; i < 4; i++) p[i]  = Ps[k][q0 + i];
            #pragma unroll
            for (int j = 0; j < 4; j++) vv[j] = Vs[k][d0 + j];
            #pragma unroll
            for (int i = 0; i < 4; i++)
                #pragma unroll
                for (int j = 0; j < 4; j++)
                    o[i][j] = fmaf(p[i], vv[j], o[i][j]);
        }
        __syncthreads();
    }

    // epilogue: gate by u, write back in [B,S,D] layout
    #pragma unroll
    for (int i = 0; i < 4; i++) {
        const int gq = qt*QT + q0 + i;
        const float4 u = *(const float4*)&ubase[(size_t)gq * rs + d0];
        float4 r;
        r.x = o[i][0] * u.x; r.y = o[i][1] * u.y;
        r.z = o[i][2] * u.z; r.w = o[i][3] * u.w;
        *(float4*)&y[((size_t)b * Ss + gq) * Dd + head * HD + d0] = r;
    }
}

// ---------------- LayerNorm (one row / CTA, 256 threads, 4 elems/thread) -----
__device__ __forceinline__ float block_sum(float v, float* sbuf) {
    #pragma unroll
    for (int o = 16; o > 0; o >>= 1) v += __shfl_down_sync(0xffffffffu, v, o);
    const int lane = threadIdx.x & 31, w = threadIdx.x >> 5;
    if (lane == 0) sbuf[w] = v;
    __syncthreads();
    if (w == 0) {
        v = (lane < 8) ? sbuf[lane] : 0.f;
        #pragma unroll
        for (int o = 4; o > 0; o >>= 1) v += __shfl_down_sync(0xffffffffu, v, o);
        if (lane == 0) sbuf[0] = v;
    }
    __syncthreads();
    float r = sbuf[0];
    __syncthreads();
    return r;
}

__global__ __launch_bounds__(256)
void ln_kernel(const float* __restrict__ in, const float* __restrict__ res,
               const float* __restrict__ g, const float* __restrict__ beta,
               float* __restrict__ out) {
    __shared__ float sbuf[8];
    const size_t row = blockIdx.x;
    const int c = threadIdx.x * 4;
    float4 v = *(const float4*)&in[row * Dd + c];
    if (res) {
        float4 r = *(const float4*)&res[row * Dd + c];
        v.x += r.x; v.y += r.y; v.z += r.z; v.w += r.w;
    }
    const float total = block_sum(v.x + v.y + v.z + v.w, sbuf);
    const float mu = total * (1.f / Dd);
    float dx = v.x - mu, dy = v.y - mu, dz = v.z - mu, dw = v.w - mu;
    const float ssq = block_sum(dx*dx + dy*dy + dz*dz + dw*dw, sbuf);
    const float inv = rsqrtf(ssq * (1.f / Dd) + EPS);
    float4 gv = *(const float4*)&g[c];
    float4 bv = *(const float4*)&beta[c];
    float4 r;
    r.x = dx * inv * gv.x + bv.x;
    r.y = dy * inv * gv.y + bv.y;
    r.z = dz * inv * gv.z + bv.z;
    r.w = dw * inv * gv.w + bv.w;
    *(float4*)&out[row * Dd + c] = r;
}

// ---------------- launch ------------------------------------------------------
extern "C" void kernel_launch(void* const* d_in, const int* in_sizes, int n_in,
                              void* d_out, int out_size) {
    const float* x     = (const float*)d_in[0];
    // d_in[1] = mask (int32) — causal, handled analytically
    const float* w1    = (const float*)d_in[2];
    const float* b1    = (const float*)d_in[3];
    const float* w2    = (const float*)d_in[4];
    const float* b2    = (const float*)d_in[5];
    const float* g1    = (const float*)d_in[6];
    const float* beta1 = (const float*)d_in[7];
    const float* g2    = (const float*)d_in[8];
    const float* beta2 = (const float*)d_in[9];
    const float* pos_w = (const float*)d_in[10];
    float* out = (float*)d_out;

    float *hbuf, *ybuf, *zbuf, *tbuf;
    cudaGetSymbolAddress((void**)&hbuf, g_h);
    cudaGetSymbolAddress((void**)&ybuf, g_y);
    cudaGetSymbolAddress((void**)&zbuf, g_z);
    cudaGetSymbolAddress((void**)&tbuf, g_t);

    // 1) h = silu(x @ w1^T + b1)   [4096 x 4096]
    gemm_bias_kernel<true><<<dim3(FOURD/BN, NTOK/BM), 256>>>(
        x, w1, b1, hbuf, NTOK, FOURD, Dd);

    // 2) fused attention + u gate -> g_y
    const int attn_smem = 4 * 64 * PADW * (int)sizeof(float);
    cudaFuncSetAttribute(attn_kernel, cudaFuncAttributeMaxDynamicSharedMemorySize, attn_smem);
    attn_kernel<<<dim3(Ss/QT, Hh, Bb), 256, attn_smem>>>(pos_w, ybuf);

    // 3) LN1
    ln_kernel<<<NTOK, 256>>>(ybuf, nullptr, g1, beta1, zbuf);

    // 4) t = z @ w2^T + b2   [4096 x 1024]
    gemm_bias_kernel<false><<<dim3(Dd/BN, NTOK/BM), 256>>>(
        zbuf, w2, b2, tbuf, NTOK, Dd, Dd);

    // 5) out = LN(t + x)
    ln_kernel<<<NTOK, 256>>>(tbuf, x, g2, beta2, out);
}

// round 3
// speedup vs baseline: 1.4564x; 1.4564x over previous
#include <cuda_runtime.h>
#include <cuda_bf16.h>
#include <cstdint>
#include <cstddef>

// Problem constants
#define Bb 2
#define Ss 2048
#define Dd 1024
#define Hh 16
#define HDim 64
#define Mm 4096
#define NTOK (Bb*Ss)          // 4096
#define FOURD (4*Dd)          // 4096
#define EPS 1e-5f

// ---------------- scratch ----------------------------------------------------
__device__ float g_h[(size_t)NTOK * FOURD];   // silu(x@w1^T+b1)
__device__ float g_y[(size_t)NTOK * Dd];      // gated attention out
__device__ float g_z[(size_t)NTOK * Dd];      // LN1 out
__device__ float g_t[(size_t)NTOK * Dd];      // GEMM2 out

// ============================================================================
// HMMA bf16 GEMM: C = [silu](A @ W^T + bias)
// A [Mrows,K] fp32 row-major, W [N,K] fp32 row-major, C [Mrows,N] fp32.
// bf16 hi/lo split, 3-term compensated mma.sync.m16n8k16 (fp32 accum).
// Tile 128x128 per CTA (8 warps, 64x32 warp tiles), K-chunk 32, double buffer.
// ============================================================================
#define BM 128
#define BN 128
#define KC 32
#define PW 20                          // SMEM row pitch in 32-bit words (80 B)
#define TILE_W32 (128 * PW)            // one 128-row tile, in words
#define STG_W32  (4 * TILE_W32)        // Ah, Al, Bh, Bl
#define GSMEM_BYTES (2 * STG_W32 * 4)  // double buffered = 81920 B

__device__ __forceinline__ void mma_bf16(float* c, const uint32_t* a, const uint32_t* b) {
    asm volatile(
        "mma.sync.aligned.m16n8k16.row.col.f32.bf16.bf16.f32 "
        "{%0,%1,%2,%3}, {%4,%5,%6,%7}, {%8,%9}, {%0,%1,%2,%3};"
        : "+f"(c[0]), "+f"(c[1]), "+f"(c[2]), "+f"(c[3])
        : "r"(a[0]), "r"(a[1]), "r"(a[2]), "r"(a[3]), "r"(b[0]), "r"(b[1]));
}

__device__ __forceinline__ uint2 cvt_hi(float4 g, float4* rem) {
    __nv_bfloat16 h0 = __float2bfloat16(g.x), h1 = __float2bfloat16(g.y);
    __nv_bfloat16 h2 = __float2bfloat16(g.z), h3 = __float2bfloat16(g.w);
    rem->x = g.x - __bfloat162float(h0);
    rem->y = g.y - __bfloat162float(h1);
    rem->z = g.z - __bfloat162float(h2);
    rem->w = g.w - __bfloat162float(h3);
    __nv_bfloat162 p0(h0, h1), p1(h2, h3);
    return make_uint2(*(uint32_t*)&p0, *(uint32_t*)&p1);
}
__device__ __forceinline__ uint2 cvt_lo(float4 g) {
    __nv_bfloat16 l0 = __float2bfloat16(g.x), l1 = __float2bfloat16(g.y);
    __nv_bfloat16 l2 = __float2bfloat16(g.z), l3 = __float2bfloat16(g.w);
    __nv_bfloat162 p0(l0, l1), p1(l2, l3);
    return make_uint2(*(uint32_t*)&p0, *(uint32_t*)&p1);
}

template<bool SILU>
__global__ __launch_bounds__(256)
void hmma_gemm(const float* __restrict__ A, const float* __restrict__ W,
               const float* __restrict__ bias, float* __restrict__ C,
               int N, int K) {
    extern __shared__ __align__(16) uint32_t sw[];
    const int tid  = threadIdx.x;
    const int wid  = tid >> 5;
    const int lane = tid & 31;
    const int g = lane >> 2, t = lane & 3;
    const int m0 = blockIdx.y * BM;
    const int n0 = blockIdx.x * BN;
    const int wm = (wid >> 2) * 64;    // warp row offset in tile
    const int wn = (wid & 3) * 32;     // warp col offset in tile

    float acc[4][4][4];
    #pragma unroll
    for (int i = 0; i < 4; i++)
        #pragma unroll
        for (int j = 0; j < 4; j++)
            #pragma unroll
            for (int e = 0; e < 4; e++) acc[i][j][e] = 0.f;

    const int nc = K / KC;
    // per-thread GMEM staging: 4 float4 of A, 4 of W per chunk
    const int ldr = tid >> 3;          // base row (thread covers rows ldr + 32*it... no: idx mapping below)
    float4 pa[4], pb[4];

    auto load_chunk = [&](int c) {
        const int k0 = c * KC;
        #pragma unroll
        for (int it = 0; it < 4; it++) {
            int idx = it * 256 + tid;      // 0..1023 float4 slots
            int r = idx >> 3, q = idx & 7; // 128 rows x 8 float4
            pa[it] = *(const float4*)&A[(size_t)(m0 + r) * K + k0 + q * 4];
            pb[it] = *(const float4*)&W[(size_t)(n0 + r) * K + k0 + q * 4];
        }
    };
    auto store_chunk = [&](int buf) {
        uint32_t* base = sw + buf * STG_W32;
        #pragma unroll
        for (int it = 0; it < 4; it++) {
            int idx = it * 256 + tid;
            int r = idx >> 3, q = idx & 7;
            uint32_t wo = (uint32_t)(r * PW + q * 2);
            float4 rem;
            uint2 h = cvt_hi(pa[it], &rem);
            *(uint2*)(base + wo) = h;                       // A hi
            *(uint2*)(base + TILE_W32 + wo) = cvt_lo(rem);  // A lo
            h = cvt_hi(pb[it], &rem);
            *(uint2*)(base + 2*TILE_W32 + wo) = h;          // B hi
            *(uint2*)(base + 3*TILE_W32 + wo) = cvt_lo(rem);// B lo
        }
    };

    load_chunk(0);
    store_chunk(0);
    __syncthreads();

    for (int c = 0; c < nc; c++) {
        if (c + 1 < nc) load_chunk(c + 1);

        const uint32_t* Ah = sw + (c & 1) * STG_W32;
        const uint32_t* Al = Ah + TILE_W32;
        const uint32_t* Bh = Ah + 2*TILE_W32;
        const uint32_t* Bl = Ah + 3*TILE_W32;

        #pragma unroll
        for (int ks = 0; ks < 2; ks++) {
            const int kw = ks * 8 + t;
            uint32_t ah[4][4], al[4][4], bh[4][2], bl[4][2];
            #pragma unroll
            for (int mi = 0; mi < 4; mi++) {
                const int r = wm + mi * 16 + g;
                ah[mi][0] = Ah[r * PW + kw];
                ah[mi][1] = Ah[(r + 8) * PW + kw];
                ah[mi][2] = Ah[r * PW + kw + 4];
                ah[mi][3] = Ah[(r + 8) * PW + kw + 4];
                al[mi][0] = Al[r * PW + kw];
                al[mi][1] = Al[(r + 8) * PW + kw];
                al[mi][2] = Al[r * PW + kw + 4];
                al[mi][3] = Al[(r + 8) * PW + kw + 4];
            }
            #pragma unroll
            for (int nj = 0; nj < 4; nj++) {
                const int r = wn + nj * 8 + g;
                bh[nj][0] = Bh[r * PW + kw];
                bh[nj][1] = Bh[r * PW + kw + 4];
                bl[nj][0] = Bl[r * PW + kw];
                bl[nj][1] = Bl[r * PW + kw + 4];
            }
            #pragma unroll
            for (int mi = 0; mi < 4; mi++)
                #pragma unroll
                for (int nj = 0; nj < 4; nj++) {
                    mma_bf16(acc[mi][nj], ah[mi], bh[nj]);
                    mma_bf16(acc[mi][nj], ah[mi], bl[nj]);
                    mma_bf16(acc[mi][nj], al[mi], bh[nj]);
                }
        }

        if (c + 1 < nc) {
            __syncthreads();
            store_chunk((c + 1) & 1);
            __syncthreads();
        }
    }

    // epilogue
    #pragma unroll
    for (int mi = 0; mi < 4; mi++) {
        const int r0 = m0 + wm + mi * 16 + g;
        #pragma unroll
        for (int nj = 0; nj < 4; nj++) {
            const int cc = n0 + wn + nj * 8 + 2 * t;
            const float b0 = bias[cc], b1 = bias[cc + 1];
            float v0 = acc[mi][nj][0] + b0;
            float v1 = acc[mi][nj][1] + b1;
            float v2 = acc[mi][nj][2] + b0;
            float v3 = acc[mi][nj][3] + b1;
            if (SILU) {
                v0 = v0 / (1.f + __expf(-v0));
                v1 = v1 / (1.f + __expf(-v1));
                v2 = v2 / (1.f + __expf(-v2));
                v3 = v3 / (1.f + __expf(-v3));
            }
            *(float2*)&C[(size_t)r0 * N + cc]       = make_float2(v0, v1);
            *(float2*)&C[(size_t)(r0 + 8) * N + cc] = make_float2(v2, v3);
        }
    }
}

// ============================================================================
// fused causal silu-attention + u-gate (unchanged, proven correct)
// ============================================================================
#define QT 64
#define PADW 68

__global__ __launch_bounds__(256)
void attn_kernel(const float* __restrict__ pos_w, float* __restrict__ y) {
    extern __shared__ float smf[];
    float (*Qs)[PADW] = (float(*)[PADW])smf;
    float (*Ks)[PADW] = (float(*)[PADW])(smf + 64*PADW);
    float (*Vs)[PADW] = (float(*)[PADW])(smf + 2*64*PADW);
    float (*Ps)[PADW] = (float(*)[PADW])(smf + 3*64*PADW);

    const int qt   = blockIdx.x;
    const int head = blockIdx.y;
    const int b    = blockIdx.z;
    const int tid  = threadIdx.x;
    const int tx = tid & 15, ty = tid >> 4;
    const int q0 = ty * 4, d0 = tx * 4;

    const size_t rs = FOURD;
    const float* ubase = g_h + (size_t)b * Ss * rs + 0*Dd + head * HDim;
    const float* qbase = g_h + (size_t)b * Ss * rs + 1*Dd + head * HDim;
    const float* kbase = g_h + (size_t)b * Ss * rs + 2*Dd + head * HDim;
    const float* vbase = g_h + (size_t)b * Ss * rs + 3*Dd + head * HDim;

    #pragma unroll
    for (int it = 0; it < 4; it++) {
        int idx = it * 256 + tid;
        int r = idx >> 4;
        int c4 = idx & 15;
        float4 g = *(const float4*)&qbase[(size_t)(qt*QT + r) * rs + c4*4];
        Qs[c4*4+0][r] = g.x; Qs[c4*4+1][r] = g.y;
        Qs[c4*4+2][r] = g.z; Qs[c4*4+3][r] = g.w;
    }

    float o[4][4];
    #pragma unroll
    for (int i = 0; i < 4; i++)
        #pragma unroll
        for (int j = 0; j < 4; j++) o[i][j] = 0.f;

    for (int jt = 0; jt <= qt; jt++) {
        #pragma unroll
        for (int it = 0; it < 4; it++) {
            int idx = it * 256 + tid;
            int r = idx >> 4;
            int c4 = idx & 15;
            float4 gk = *(const float4*)&kbase[(size_t)(jt*QT + r) * rs + c4*4];
            Ks[c4*4+0][r] = gk.x; Ks[c4*4+1][r] = gk.y;
            Ks[c4*4+2][r] = gk.z; Ks[c4*4+3][r] = gk.w;
            float4 gv = *(const float4*)&vbase[(size_t)(jt*QT + r) * rs + c4*4];
            *(float4*)&Vs[r][c4*4] = gv;
        }
        __syncthreads();

        float s[4][4];
        #pragma unroll
        for (int i = 0; i < 4; i++)
            #pragma unroll
            for (int j = 0; j < 4; j++) s[i][j] = 0.f;
        #pragma unroll 8
        for (int d = 0; d < 64; d++) {
            float a[4], bb[4];
            #pragma unroll
            for (int i = 0; i < 4; i++) a[i]  = Qs[d][q0 + i];
            #pragma unroll
            for (int j = 0; j < 4; j++) bb[j] = Ks[d][tx*4 + j];
            #pragma unroll
            for (int i = 0; i < 4; i++)
                #pragma unroll
                for (int j = 0; j < 4; j++)
                    s[i][j] = fmaf(a[i], bb[j], s[i][j]);
        }
        #pragma unroll
        for (int i = 0; i < 4; i++) {
            const int gq = qt*QT + q0 + i;
            #pragma unroll
            for (int j = 0; j < 4; j++) {
                const int gk = jt*QT + tx*4 + j;
                float v = s[i][j] + pos_w[Mm - 1 + gk - gq];
                v = v / (1.f + __expf(-v));
                if (gk > gq) v = 0.f;
                Ps[tx*4 + j][q0 + i] = v;
            }
        }
        __syncthreads();

        #pragma unroll 8
        for (int k = 0; k < 64; k++) {
            float p[4], vv[4];
            #pragma unroll
            for (int i = 0; i < 4; i++) p[i]  = Ps[k][q0 + i];
            #pragma unroll
            for (int j = 0; j < 4; j++) vv[j] = Vs[k][d0 + j];
            #pragma unroll
            for (int i = 0; i < 4; i++)
                #pragma unroll
                for (int j = 0; j < 4; j++)
                    o[i][j] = fmaf(p[i], vv[j], o[i][j]);
        }
        __syncthreads();
    }

    #pragma unroll
    for (int i = 0; i < 4; i++) {
        const int gq = qt*QT + q0 + i;
        const float4 u = *(const float4*)&ubase[(size_t)gq * rs + d0];
        float4 r;
        r.x = o[i][0] * u.x; r.y = o[i][1] * u.y;
        r.z = o[i][2] * u.z; r.w = o[i][3] * u.w;
        *(float4*)&y[((size_t)b * Ss + gq) * Dd + head * HDim + d0] = r;
    }
}

// ---------------- LayerNorm ---------------------------------------------------
__device__ __forceinline__ float block_sum(float v, float* sbuf) {
    #pragma unroll
    for (int o = 16; o > 0; o >>= 1) v += __shfl_down_sync(0xffffffffu, v, o);
    const int lane = threadIdx.x & 31, w = threadIdx.x >> 5;
    if (lane == 0) sbuf[w] = v;
    __syncthreads();
    if (w == 0) {
        v = (lane < 8) ? sbuf[lane] : 0.f;
        #pragma unroll
        for (int o = 4; o > 0; o >>= 1) v += __shfl_down_sync(0xffffffffu, v, o);
        if (lane == 0) sbuf[0] = v;
    }
    __syncthreads();
    float r = sbuf[0];
    __syncthreads();
    return r;
}

__global__ __launch_bounds__(256)
void ln_kernel(const float* __restrict__ in, const float* __restrict__ res,
               const float* __restrict__ g, const float* __restrict__ beta,
               float* __restrict__ out) {
    __shared__ float sbuf[8];
    const size_t row = blockIdx.x;
    const int c = threadIdx.x * 4;
    float4 v = *(const float4*)&in[row * Dd + c];
    if (res) {
        float4 r = *(const float4*)&res[row * Dd + c];
        v.x += r.x; v.y += r.y; v.z += r.z; v.w += r.w;
    }
    const float total = block_sum(v.x + v.y + v.z + v.w, sbuf);
    const float mu = total * (1.f / Dd);
    float dx = v.x - mu, dy = v.y - mu, dz = v.z - mu, dw = v.w - mu;
    const float ssq = block_sum(dx*dx + dy*dy + dz*dz + dw*dw, sbuf);
    const float inv = rsqrtf(ssq * (1.f / Dd) + EPS);
    float4 gv = *(const float4*)&g[c];
    float4 bv = *(const float4*)&beta[c];
    float4 r;
    r.x = dx * inv * gv.x + bv.x;
    r.y = dy * inv * gv.y + bv.y;
    r.z = dz * inv * gv.z + bv.z;
    r.w = dw * inv * gv.w + bv.w;
    *(float4*)&out[row * Dd + c] = r;
}

// ---------------- launch ------------------------------------------------------
extern "C" void kernel_launch(void* const* d_in, const int* in_sizes, int n_in,
                              void* d_out, int out_size) {
    const float* x     = (const float*)d_in[0];
    const float* w1    = (const float*)d_in[2];
    const float* b1    = (const float*)d_in[3];
    const float* w2    = (const float*)d_in[4];
    const float* b2    = (const float*)d_in[5];
    const float* g1    = (const float*)d_in[6];
    const float* beta1 = (const float*)d_in[7];
    const float* g2    = (const float*)d_in[8];
    const float* beta2 = (const float*)d_in[9];
    const float* pos_w = (const float*)d_in[10];
    float* out = (float*)d_out;

    float *hbuf, *ybuf, *zbuf, *tbuf;
    cudaGetSymbolAddress((void**)&hbuf, g_h);
    cudaGetSymbolAddress((void**)&ybuf, g_y);
    cudaGetSymbolAddress((void**)&zbuf, g_z);
    cudaGetSymbolAddress((void**)&tbuf, g_t);

    cudaFuncSetAttribute(hmma_gemm<true>,  cudaFuncAttributeMaxDynamicSharedMemorySize, GSMEM_BYTES);
    cudaFuncSetAttribute(hmma_gemm<false>, cudaFuncAttributeMaxDynamicSharedMemorySize, GSMEM_BYTES);

    // 1) h = silu(x @ w1^T + b1)   [4096 x 4096], K=1024
    hmma_gemm<true><<<dim3(FOURD/BN, NTOK/BM), 256, GSMEM_BYTES>>>(
        x, w1, b1, hbuf, FOURD, Dd);

    // 2) fused attention + u gate -> g_y
    const int attn_smem = 4 * 64 * PADW * (int)sizeof(float);
    cudaFuncSetAttribute(attn_kernel, cudaFuncAttributeMaxDynamicSharedMemorySize, attn_smem);
    attn_kernel<<<dim3(Ss/QT, Hh, Bb), 256, attn_smem>>>(pos_w, ybuf);

    // 3) LN1
    ln_kernel<<<NTOK, 256>>>(ybuf, nullptr, g1, beta1, zbuf);

    // 4) t = z @ w2^T + b2   [4096 x 1024], K=1024
    hmma_gemm<false><<<dim3(Dd/BN, NTOK/BM), 256, GSMEM_BYTES>>>(
        zbuf, w2, b2, tbuf, Dd, Dd);

    // 5) out = LN(t + x)
    ln_kernel<<<NTOK, 256>>>(tbuf, x, g2, beta2, out);
}

// round 4
// speedup vs baseline: 1.7995x; 1.2356x over previous
#include <cuda_runtime.h>
#include <cuda_bf16.h>
#include <cstdint>
#include <cstddef>

// Problem constants
#define Bb 2
#define Ss 2048
#define Dd 1024
#define Hh 16
#define HDim 64
#define Mm 4096
#define NTOK (Bb*Ss)          // 4096
#define FOURD (4*Dd)          // 4096
#define EPS 1e-5f

// ---------------- scratch ----------------------------------------------------
__device__ float g_h[(size_t)NTOK * FOURD];   // silu(x@w1^T+b1)
__device__ float g_y[(size_t)NTOK * Dd];      // gated attention out
__device__ float g_z[(size_t)NTOK * Dd];      // LN1 out
__device__ float g_t[(size_t)NTOK * Dd];      // GEMM2 out

// ---------------- common HMMA helpers -----------------------------------------
__device__ __forceinline__ void mma_bf16(float* c, const uint32_t* a, const uint32_t* b) {
    asm volatile(
        "mma.sync.aligned.m16n8k16.row.col.f32.bf16.bf16.f32 "
        "{%0,%1,%2,%3}, {%4,%5,%6,%7}, {%8,%9}, {%0,%1,%2,%3};"
        : "+f"(c[0]), "+f"(c[1]), "+f"(c[2]), "+f"(c[3])
        : "r"(a[0]), "r"(a[1]), "r"(a[2]), "r"(a[3]), "r"(b[0]), "r"(b[1]));
}
__device__ __forceinline__ uint2 cvt_hi(float4 g, float4* rem) {
    __nv_bfloat16 h0 = __float2bfloat16(g.x), h1 = __float2bfloat16(g.y);
    __nv_bfloat16 h2 = __float2bfloat16(g.z), h3 = __float2bfloat16(g.w);
    rem->x = g.x - __bfloat162float(h0);
    rem->y = g.y - __bfloat162float(h1);
    rem->z = g.z - __bfloat162float(h2);
    rem->w = g.w - __bfloat162float(h3);
    __nv_bfloat162 p0(h0, h1), p1(h2, h3);
    return make_uint2(*(uint32_t*)&p0, *(uint32_t*)&p1);
}
__device__ __forceinline__ uint2 cvt_lo(float4 g) {
    __nv_bfloat16 l0 = __float2bfloat16(g.x), l1 = __float2bfloat16(g.y);
    __nv_bfloat16 l2 = __float2bfloat16(g.z), l3 = __float2bfloat16(g.w);
    __nv_bfloat162 p0(l0, l1), p1(l2, l3);
    return make_uint2(*(uint32_t*)&p0, *(uint32_t*)&p1);
}
__device__ __forceinline__ uint32_t pack_bf2(float a, float b) {
    __nv_bfloat162 p(__float2bfloat16(a), __float2bfloat16(b));
    return *(uint32_t*)&p;
}
__device__ __forceinline__ float silu_f(float v) {
    return v / (1.f + __expf(-v));
}

// ============================================================================
// HMMA bf16 GEMM (unchanged from R3, proven)
// ============================================================================
#define BM 128
#define BN 128
#define KC 32
#define PW 20
#define TILE_W32 (128 * PW)
#define STG_W32  (4 * TILE_W32)
#define GSMEM_BYTES (2 * STG_W32 * 4)

template<bool SILU>
__global__ __launch_bounds__(256)
void hmma_gemm(const float* __restrict__ A, const float* __restrict__ W,
               const float* __restrict__ bias, float* __restrict__ C,
               int N, int K) {
    extern __shared__ __align__(16) uint32_t sw[];
    const int tid  = threadIdx.x;
    const int wid  = tid >> 5;
    const int lane = tid & 31;
    const int g = lane >> 2, t = lane & 3;
    const int m0 = blockIdx.y * BM;
    const int n0 = blockIdx.x * BN;
    const int wm = (wid >> 2) * 64;
    const int wn = (wid & 3) * 32;

    float acc[4][4][4];
    #pragma unroll
    for (int i = 0; i < 4; i++)
        #pragma unroll
        for (int j = 0; j < 4; j++)
            #pragma unroll
            for (int e = 0; e < 4; e++) acc[i][j][e] = 0.f;

    const int nc = K / KC;
    float4 pa[4], pb[4];

    auto load_chunk = [&](int c) {
        const int k0 = c * KC;
        #pragma unroll
        for (int it = 0; it < 4; it++) {
            int idx = it * 256 + tid;
            int r = idx >> 3, q = idx & 7;
            pa[it] = *(const float4*)&A[(size_t)(m0 + r) * K + k0 + q * 4];
            pb[it] = *(const float4*)&W[(size_t)(n0 + r) * K + k0 + q * 4];
        }
    };
    auto store_chunk = [&](int buf) {
        uint32_t* base = sw + buf * STG_W32;
        #pragma unroll
        for (int it = 0; it < 4; it++) {
            int idx = it * 256 + tid;
            int r = idx >> 3, q = idx & 7;
            uint32_t wo = (uint32_t)(r * PW + q * 2);
            float4 rem;
            uint2 h = cvt_hi(pa[it], &rem);
            *(uint2*)(base + wo) = h;
            *(uint2*)(base + TILE_W32 + wo) = cvt_lo(rem);
            h = cvt_hi(pb[it], &rem);
            *(uint2*)(base + 2*TILE_W32 + wo) = h;
            *(uint2*)(base + 3*TILE_W32 + wo) = cvt_lo(rem);
        }
    };

    load_chunk(0);
    store_chunk(0);
    __syncthreads();

    for (int c = 0; c < nc; c++) {
        if (c + 1 < nc) load_chunk(c + 1);

        const uint32_t* Ah = sw + (c & 1) * STG_W32;
        const uint32_t* Al = Ah + TILE_W32;
        const uint32_t* Bh = Ah + 2*TILE_W32;
        const uint32_t* Bl = Ah + 3*TILE_W32;

        #pragma unroll
        for (int ks = 0; ks < 2; ks++) {
            const int kw = ks * 8 + t;
            uint32_t ah[4][4], al[4][4], bh[4][2], bl[4][2];
            #pragma unroll
            for (int mi = 0; mi < 4; mi++) {
                const int r = wm + mi * 16 + g;
                ah[mi][0] = Ah[r * PW + kw];
                ah[mi][1] = Ah[(r + 8) * PW + kw];
                ah[mi][2] = Ah[r * PW + kw + 4];
                ah[mi][3] = Ah[(r + 8) * PW + kw + 4];
                al[mi][0] = Al[r * PW + kw];
                al[mi][1] = Al[(r + 8) * PW + kw];
                al[mi][2] = Al[r * PW + kw + 4];
                al[mi][3] = Al[(r + 8) * PW + kw + 4];
            }
            #pragma unroll
            for (int nj = 0; nj < 4; nj++) {
                const int r = wn + nj * 8 + g;
                bh[nj][0] = Bh[r * PW + kw];
                bh[nj][1] = Bh[r * PW + kw + 4];
                bl[nj][0] = Bl[r * PW + kw];
                bl[nj][1] = Bl[r * PW + kw + 4];
            }
            #pragma unroll
            for (int mi = 0; mi < 4; mi++)
                #pragma unroll
                for (int nj = 0; nj < 4; nj++) {
                    mma_bf16(acc[mi][nj], ah[mi], bh[nj]);
                    mma_bf16(acc[mi][nj], ah[mi], bl[nj]);
                    mma_bf16(acc[mi][nj], al[mi], bh[nj]);
                }
        }

        if (c + 1 < nc) {
            __syncthreads();
            store_chunk((c + 1) & 1);
            __syncthreads();
        }
    }

    #pragma unroll
    for (int mi = 0; mi < 4; mi++) {
        const int r0 = m0 + wm + mi * 16 + g;
        #pragma unroll
        for (int nj = 0; nj < 4; nj++) {
            const int cc = n0 + wn + nj * 8 + 2 * t;
            const float b0 = bias[cc], b1 = bias[cc + 1];
            float v0 = acc[mi][nj][0] + b0;
            float v1 = acc[mi][nj][1] + b1;
            float v2 = acc[mi][nj][2] + b0;
            float v3 = acc[mi][nj][3] + b1;
            if (SILU) {
                v0 = silu_f(v0); v1 = silu_f(v1);
                v2 = silu_f(v2); v3 = silu_f(v3);
            }
            *(float2*)&C[(size_t)r0 * N + cc]       = make_float2(v0, v1);
            *(float2*)&C[(size_t)(r0 + 8) * N + cc] = make_float2(v2, v3);
        }
    }
}

// ============================================================================
// HMMA flash attention: y = u * (silu(QK^T + bias) [causal]) @ V
// CTA = 128 q rows of one (b,h); 8 warps, each owns a 16-row q slab and the
// FULL 64-key tile, so P converts from S accumulators to A-fragments entirely
// in registers. 3-term bf16 compensation on both QK^T and PV.
// ============================================================================
#define AQT 128               // q rows per CTA
#define AKT 64                // k tile
#define APW 36                // SMEM pitch in 32-bit words (72 bf16 = 144 B)

// SMEM word offsets
#define QH_OFF 0
#define QL_OFF (128 * APW)                 // 4608
#define BUF_OFF (2 * 128 * APW)            // 9216
#define BUF_W  (4 * 64 * APW)              // 9216 words per buffer (Kh,Kl,Vth,Vtl)
#define KH_O 0
#define KL_O (64 * APW)
#define VTH_O (2 * 64 * APW)
#define VTL_O (3 * 64 * APW)
#define ASMEM_BYTES ((BUF_OFF + 2 * BUF_W) * 4)   // 110592 B

__global__ __launch_bounds__(256)
void attn_hmma(const float* __restrict__ pos_w, float* __restrict__ y) {
    extern __shared__ __align__(16) uint32_t aw[];
    __nv_bfloat16* ab = (__nv_bfloat16*)aw;

    const int qt   = blockIdx.x;
    const int head = blockIdx.y;
    const int b    = blockIdx.z;
    const int tid  = threadIdx.x;
    const int wid  = tid >> 5;
    const int lane = tid & 31;
    const int g = lane >> 2, t = lane & 3;

    const size_t rs = FOURD;
    const float* ubase = g_h + (size_t)b * Ss * rs + 0*Dd + head * HDim;
    const float* qbase = g_h + (size_t)b * Ss * rs + 1*Dd + head * HDim;
    const float* kbase = g_h + (size_t)b * Ss * rs + 2*Dd + head * HDim;
    const float* vbase = g_h + (size_t)b * Ss * rs + 3*Dd + head * HDim;

    const int q_cta = qt * AQT;          // first global q row of CTA
    const int jtmax = 2 * qt + 1;        // last k tile index (inclusive)

    // ---- load Q tile (128 x 64) as bf16 hi/lo ----
    #pragma unroll
    for (int it = 0; it < 8; it++) {
        int idx = it * 256 + tid;        // 0..2047 float4 slots
        int r = idx >> 4, c = (idx & 15) * 4;
        float4 v = *(const float4*)&qbase[(size_t)(q_cta + r) * rs + c];
        float4 rem;
        uint2 h = cvt_hi(v, &rem);
        uint32_t wo = (uint32_t)(r * APW + c / 2);
        *(uint2*)(aw + QH_OFF + wo) = h;
        *(uint2*)(aw + QL_OFF + wo) = cvt_lo(rem);
    }

    float4 pk[4], pv[4];
    auto load_kv = [&](int jt) {
        const int k0 = jt * AKT;
        #pragma unroll
        for (int it = 0; it < 4; it++) {
            int idx = it * 256 + tid;    // 0..1023
            int r = idx >> 4, c = (idx & 15) * 4;
            pk[it] = *(const float4*)&kbase[(size_t)(k0 + r) * rs + c];
            pv[it] = *(const float4*)&vbase[(size_t)(k0 + r) * rs + c];
        }
    };
    auto store_kv = [&](int buf) {
        uint32_t* base = aw + BUF_OFF + buf * BUF_W;
        __nv_bfloat16* vth = (__nv_bfloat16*)(base + VTH_O);
        __nv_bfloat16* vtl = (__nv_bfloat16*)(base + VTL_O);
        #pragma unroll
        for (int it = 0; it < 4; it++) {
            int idx = it * 256 + tid;
            int r = idx >> 4, c = (idx & 15) * 4;
            // K: row-major hi/lo
            float4 rem;
            uint2 h = cvt_hi(pk[it], &rem);
            uint32_t wo = (uint32_t)(r * APW + c / 2);
            *(uint2*)(base + KH_O + wo) = h;
            *(uint2*)(base + KL_O + wo) = cvt_lo(rem);
            // V: transposed (Vt[d][k]) hi/lo, scalar stores
            float vv[4] = {pv[it].x, pv[it].y, pv[it].z, pv[it].w};
            #pragma unroll
            for (int e = 0; e < 4; e++) {
                __nv_bfloat16 hi = __float2bfloat16(vv[e]);
                __nv_bfloat16 lo = __float2bfloat16(vv[e] - __bfloat162float(hi));
                vth[(c + e) * (2*APW) + r] = hi;
                vtl[(c + e) * (2*APW) + r] = lo;
            }
        }
    };

    load_kv(0);
    store_kv(0);
    __syncthreads();

    float O[8][4];
    #pragma unroll
    for (int nj = 0; nj < 8; nj++)
        #pragma unroll
        for (int e = 0; e < 4; e++) O[nj][e] = 0.f;

    const int q_warp = q_cta + wid * 16;        // warp's first q row
    const uint32_t* QHp = aw + QH_OFF;
    const uint32_t* QLp = aw + QL_OFF;

    for (int jt = 0; jt <= jtmax; jt++) {
        if (jt < jtmax) load_kv(jt + 1);

        const uint32_t* base = aw + BUF_OFF + (jt & 1) * BUF_W;
        const uint32_t* KHp  = base + KH_O;
        const uint32_t* KLp  = base + KL_O;
        const uint32_t* VHp  = base + VTH_O;
        const uint32_t* VLp  = base + VTL_O;

        // causal skip: entire warp tile above diagonal
        if (jt * AKT <= q_warp + 15) {
            // ---- S = Q @ K^T  (m16 x n64 x k64) ----
            float S[8][4];
            #pragma unroll
            for (int nj = 0; nj < 8; nj++)
                #pragma unroll
                for (int e = 0; e < 4; e++) S[nj][e] = 0.f;

            #pragma unroll
            for (int ks = 0; ks < 4; ks++) {
                const int qa = (wid * 16 + g) * APW + ks * 8 + t;
                uint32_t ah[4], al[4];
                ah[0] = QHp[qa];           ah[1] = QHp[qa + 8*APW];
                ah[2] = QHp[qa + 4];       ah[3] = QHp[qa + 8*APW + 4];
                al[0] = QLp[qa];           al[1] = QLp[qa + 8*APW];
                al[2] = QLp[qa + 4];       al[3] = QLp[qa + 8*APW + 4];
                #pragma unroll
                for (int nj = 0; nj < 8; nj++) {
                    const int ka = (nj * 8 + g) * APW + ks * 8 + t;
                    uint32_t bh[2], bl[2];
                    bh[0] = KHp[ka]; bh[1] = KHp[ka + 4];
                    bl[0] = KLp[ka]; bl[1] = KLp[ka + 4];
                    mma_bf16(S[nj], ah, bh);
                    mma_bf16(S[nj], ah, bl);
                    mma_bf16(S[nj], al, bh);
                }
            }

            // ---- P = mask(silu(S + bias)); PV accumulate ----
            const int qg0 = q_warp + g;        // global q row of accum row g
            #pragma unroll
            for (int ks2 = 0; ks2 < 4; ks2++) {
                uint32_t ph[4], pl[4];
                #pragma unroll
                for (int half = 0; half < 2; half++) {
                    const float* sc = S[2*ks2 + half];
                    const int kc = jt * AKT + (2*ks2 + half) * 8 + 2*t;
                    float p00 = silu_f(sc[0] + pos_w[Mm - 1 + kc     - qg0]);
                    float p01 = silu_f(sc[1] + pos_w[Mm - 1 + kc + 1 - qg0]);
                    float p10 = silu_f(sc[2] + pos_w[Mm - 1 + kc     - (qg0+8)]);
                    float p11 = silu_f(sc[3] + pos_w[Mm - 1 + kc + 1 - (qg0+8)]);
                    if (kc     > qg0)   p00 = 0.f;
                    if (kc + 1 > qg0)   p01 = 0.f;
                    if (kc     > qg0+8) p10 = 0.f;
                    if (kc + 1 > qg0+8) p11 = 0.f;
                    __nv_bfloat16 h00 = __float2bfloat16(p00);
                    __nv_bfloat16 h01 = __float2bfloat16(p01);
                    __nv_bfloat16 h10 = __float2bfloat16(p10);
                    __nv_bfloat16 h11 = __float2bfloat16(p11);
                    __nv_bfloat162 hp0(h00, h01), hp1(h10, h11);
                    __nv_bfloat162 lp0(__float2bfloat16(p00 - __bfloat162float(h00)),
                                       __float2bfloat16(p01 - __bfloat162float(h01)));
                    __nv_bfloat162 lp1(__float2bfloat16(p10 - __bfloat162float(h10)),
                                       __float2bfloat16(p11 - __bfloat162float(h11)));
                    ph[0 + half*2] = *(uint32_t*)&hp0;
                    ph[1 + half*2] = *(uint32_t*)&hp1;
                    pl[0 + half*2] = *(uint32_t*)&lp0;
                    pl[1 + half*2] = *(uint32_t*)&lp1;
                }
                #pragma unroll
                for (int nj = 0; nj < 8; nj++) {
                    const int va = (nj * 8 + g) * APW + ks2 * 8 + t;
                    uint32_t vh[2], vl[2];
                    vh[0] = VHp[va]; vh[1] = VHp[va + 4];
                    vl[0] = VLp[va]; vl[1] = VLp[va + 4];
                    mma_bf16(O[nj], ph, vh);
                    mma_bf16(O[nj], ph, vl);
                    mma_bf16(O[nj], pl, vh);
                }
            }
        }

        if (jt < jtmax) {
            store_kv((jt + 1) & 1);
            __syncthreads();
        }
    }

    // ---- epilogue: gate by u, store to y [B,S,D] ----
    #pragma unroll
    for (int nj = 0; nj < 8; nj++) {
        const int d = nj * 8 + 2 * t;
        #pragma unroll
        for (int half = 0; half < 2; half++) {
            const int q = q_warp + g + half * 8;
            const float2 u = *(const float2*)&ubase[(size_t)q * rs + d];
            float2 r;
            r.x = O[nj][half*2 + 0] * u.x;
            r.y = O[nj][half*2 + 1] * u.y;
            *(float2*)&y[((size_t)b * Ss + q) * Dd + head * HDim + d] = r;
        }
    }
}

// ---------------- LayerNorm ---------------------------------------------------
__device__ __forceinline__ float block_sum(float v, float* sbuf) {
    #pragma unroll
    for (int o = 16; o > 0; o >>= 1) v += __shfl_down_sync(0xffffffffu, v, o);
    const int lane = threadIdx.x & 31, w = threadIdx.x >> 5;
    if (lane == 0) sbuf[w] = v;
    __syncthreads();
    if (w == 0) {
        v = (lane < 8) ? sbuf[lane] : 0.f;
        #pragma unroll
        for (int o = 4; o > 0; o >>= 1) v += __shfl_down_sync(0xffffffffu, v, o);
        if (lane == 0) sbuf[0] = v;
    }
    __syncthreads();
    float r = sbuf[0];
    __syncthreads();
    return r;
}

__global__ __launch_bounds__(256)
void ln_kernel(const float* __restrict__ in, const float* __restrict__ res,
               const float* __restrict__ g, const float* __restrict__ beta,
               float* __restrict__ out) {
    __shared__ float sbuf[8];
    const size_t row = blockIdx.x;
    const int c = threadIdx.x * 4;
    float4 v = *(const float4*)&in[row * Dd + c];
    if (res) {
        float4 r = *(const float4*)&res[row * Dd + c];
        v.x += r.x; v.y += r.y; v.z += r.z; v.w += r.w;
    }
    const float total = block_sum(v.x + v.y + v.z + v.w, sbuf);
    const float mu = total * (1.f / Dd);
    float dx = v.x - mu, dy = v.y - mu, dz = v.z - mu, dw = v.w - mu;
    const float ssq = block_sum(dx*dx + dy*dy + dz*dz + dw*dw, sbuf);
    const float inv = rsqrtf(ssq * (1.f / Dd) + EPS);
    float4 gv = *(const float4*)&g[c];
    float4 bv = *(const float4*)&beta[c];
    float4 r;
    r.x = dx * inv * gv.x + bv.x;
    r.y = dy * inv * gv.y + bv.y;
    r.z = dz * inv * gv.z + bv.z;
    r.w = dw * inv * gv.w + bv.w;
    *(float4*)&out[row * Dd + c] = r;
}

// ---------------- launch ------------------------------------------------------
extern "C" void kernel_launch(void* const* d_in, const int* in_sizes, int n_in,
                              void* d_out, int out_size) {
    const float* x     = (const float*)d_in[0];
    const float* w1    = (const float*)d_in[2];
    const float* b1    = (const float*)d_in[3];
    const float* w2    = (const float*)d_in[4];
    const float* b2    = (const float*)d_in[5];
    const float* g1    = (const float*)d_in[6];
    const float* beta1 = (const float*)d_in[7];
    const float* g2    = (const float*)d_in[8];
    const float* beta2 = (const float*)d_in[9];
    const float* pos_w = (const float*)d_in[10];
    float* out = (float*)d_out;

    float *hbuf, *ybuf, *zbuf, *tbuf;
    cudaGetSymbolAddress((void**)&hbuf, g_h);
    cudaGetSymbolAddress((void**)&ybuf, g_y);
    cudaGetSymbolAddress((void**)&zbuf, g_z);
    cudaGetSymbolAddress((void**)&tbuf, g_t);

    cudaFuncSetAttribute(hmma_gemm<true>,  cudaFuncAttributeMaxDynamicSharedMemorySize, GSMEM_BYTES);
    cudaFuncSetAttribute(hmma_gemm<false>, cudaFuncAttributeMaxDynamicSharedMemorySize, GSMEM_BYTES);
    cudaFuncSetAttribute(attn_hmma, cudaFuncAttributeMaxDynamicSharedMemorySize, ASMEM_BYTES);

    // 1) h = silu(x @ w1^T + b1)   [4096 x 4096], K=1024
    hmma_gemm<true><<<dim3(FOURD/BN, NTOK/BM), 256, GSMEM_BYTES>>>(
        x, w1, b1, hbuf, FOURD, Dd);

    // 2) fused HMMA attention + u gate -> g_y
    attn_hmma<<<dim3(Ss/AQT, Hh, Bb), 256, ASMEM_BYTES>>>(pos_w, ybuf);

    // 3) LN1
    ln_kernel<<<NTOK, 256>>>(ybuf, nullptr, g1, beta1, zbuf);

    // 4) t = z @ w2^T + b2   [4096 x 1024], K=1024
    hmma_gemm<false><<<dim3(Dd/BN, NTOK/BM), 256, GSMEM_BYTES>>>(
        zbuf, w2, b2, tbuf, Dd, Dd);

    // 5) out = LN(t + x)
    ln_kernel<<<NTOK, 256>>>(tbuf, x, g2, beta2, out);
}

// round 5
// speedup vs baseline: 1.8119x; 1.0069x over previous
#include <cuda_runtime.h>
#include <cuda_bf16.h>
#include <cstdint>
#include <cstddef>

// Problem constants
#define Bb 2
#define Ss 2048
#define Dd 1024
#define Hh 16
#define HDim 64
#define Mm 4096
#define NTOK (Bb*Ss)          // 4096
#define FOURD (4*Dd)          // 4096
#define EPS 1e-5f

// ---------------- scratch ----------------------------------------------------
__device__ float g_h[(size_t)NTOK * FOURD];   // silu(x@w1^T+b1)
__device__ float g_y[(size_t)NTOK * Dd];      // gated attention out
__device__ float g_t[(size_t)NTOK * Dd];      // GEMM2 out
// bf16 hi/lo pre-converted operands
__device__ __nv_bfloat16 g_xh[(size_t)NTOK * Dd],  g_xl[(size_t)NTOK * Dd];
__device__ __nv_bfloat16 g_w1h[(size_t)FOURD * Dd], g_w1l[(size_t)FOURD * Dd];
__device__ __nv_bfloat16 g_w2h[(size_t)Dd * Dd],   g_w2l[(size_t)Dd * Dd];
__device__ __nv_bfloat16 g_zh[(size_t)NTOK * Dd],  g_zl[(size_t)NTOK * Dd];

// ---------------- common helpers ----------------------------------------------
__device__ __forceinline__ void mma_bf16(float* c, const uint32_t* a, const uint32_t* b) {
    asm volatile(
        "mma.sync.aligned.m16n8k16.row.col.f32.bf16.bf16.f32 "
        "{%0,%1,%2,%3}, {%4,%5,%6,%7}, {%8,%9}, {%0,%1,%2,%3};"
        : "+f"(c[0]), "+f"(c[1]), "+f"(c[2]), "+f"(c[3])
        : "r"(a[0]), "r"(a[1]), "r"(a[2]), "r"(a[3]), "r"(b[0]), "r"(b[1]));
}
__device__ __forceinline__ uint2 cvt_hi(float4 g, float4* rem) {
    __nv_bfloat16 h0 = __float2bfloat16(g.x), h1 = __float2bfloat16(g.y);
    __nv_bfloat16 h2 = __float2bfloat16(g.z), h3 = __float2bfloat16(g.w);
    rem->x = g.x - __bfloat162float(h0);
    rem->y = g.y - __bfloat162float(h1);
    rem->z = g.z - __bfloat162float(h2);
    rem->w = g.w - __bfloat162float(h3);
    __nv_bfloat162 p0(h0, h1), p1(h2, h3);
    return make_uint2(*(uint32_t*)&p0, *(uint32_t*)&p1);
}
__device__ __forceinline__ uint2 cvt_lo(float4 g) {
    __nv_bfloat16 l0 = __float2bfloat16(g.x), l1 = __float2bfloat16(g.y);
    __nv_bfloat16 l2 = __float2bfloat16(g.z), l3 = __float2bfloat16(g.w);
    __nv_bfloat162 p0(l0, l1), p1(l2, l3);
    return make_uint2(*(uint32_t*)&p0, *(uint32_t*)&p1);
}
__device__ __forceinline__ float silu_f(float v) {
    return v / (1.f + __expf(-v));
}
__device__ __forceinline__ uint32_t smem_u32(const void* p) {
    uint32_t a;
    asm("{ .reg .u64 t; cvta.to.shared.u64 t, %1; cvt.u32.u64 %0, t; }"
        : "=r"(a) : "l"(p));
    return a;
}
__device__ __forceinline__ void cp16(uint32_t dst, const void* src) {
    asm volatile("cp.async.cg.shared.global [%0], [%1], 16;" :: "r"(dst), "l"(src));
}
__device__ __forceinline__ void cp_commit() {
    asm volatile("cp.async.commit_group;" ::: "memory");
}
template<int N>
__device__ __forceinline__ void cp_wait() {
    asm volatile("cp.async.wait_group %0;" :: "n"(N) : "memory");
}

// ---------------- fp32 -> bf16 hi/lo converter ---------------------------------
__global__ __launch_bounds__(256)
void cvt_kernel(const float* __restrict__ in, __nv_bfloat16* __restrict__ hi,
                __nv_bfloat16* __restrict__ lo, int n4) {
    for (int i = blockIdx.x * 256 + threadIdx.x; i < n4; i += gridDim.x * 256) {
        float4 v = *(const float4*)&in[i * 4];
        float4 rem;
        uint2 h = cvt_hi(v, &rem);
        *(uint2*)&hi[i * 4] = h;
        *(uint2*)&lo[i * 4] = cvt_lo(rem);
    }
}

// ============================================================================
// bf16 hi/lo HMMA GEMM with cp.async 3-stage pipeline
// C = [silu](A @ W^T + bias); A,W given as bf16 hi/lo pairs (K-major).
// ============================================================================
#define BM 128
#define BN 128
#define KC 32
#define PWW 20                         // SMEM row pitch in words (80 B)
#define TILEW (128 * PWW)              // words per tile (10240 B)
#define STGW  (4 * TILEW)              // words per stage (Ah,Al,Bh,Bl) 40960 B
#define NSTG 3
#define GSMEM_BYTES (NSTG * STGW * 4)  // 122880

template<bool SILU>
__global__ __launch_bounds__(256)
void hmma_gemm_cp(const __nv_bfloat16* __restrict__ Ahg, const __nv_bfloat16* __restrict__ Alg,
                  const __nv_bfloat16* __restrict__ Bhg, const __nv_bfloat16* __restrict__ Blg,
                  const float* __restrict__ bias, float* __restrict__ C,
                  int N, int K) {
    extern __shared__ __align__(16) uint32_t sw[];
    const uint32_t smb = smem_u32(sw);
    const int tid  = threadIdx.x;
    const int wid  = tid >> 5;
    const int lane = tid & 31;
    const int g = lane >> 2, t = lane & 3;
    const int m0 = blockIdx.y * BM;
    const int n0 = blockIdx.x * BN;
    const int wm = (wid >> 2) * 64;
    const int wn = (wid & 3) * 32;

    const __nv_bfloat16* tp[4] = {Ahg, Alg, Bhg, Blg};

    float acc[4][4][4];
    #pragma unroll
    for (int i = 0; i < 4; i++)
        #pragma unroll
        for (int j = 0; j < 4; j++)
            #pragma unroll
            for (int e = 0; e < 4; e++) acc[i][j][e] = 0.f;

    const int nc = K / KC;

    auto issue_chunk = [&](int c) {
        const int k0 = c * KC;
        const uint32_t stg_b = smb + (c % NSTG) * (STGW * 4);
        #pragma unroll
        for (int it = 0; it < 8; it++) {
            int idx = it * 256 + tid;          // 0..2047 16B ops
            int tile = idx >> 9;               // 0..3
            int r = (idx >> 2) & 127;
            int q = idx & 3;
            int row = (tile < 2 ? m0 : n0) + r;
            const __nv_bfloat16* src = tp[tile] + (size_t)row * K + k0 + q * 8;
            cp16(stg_b + tile * (TILEW * 4) + r * 80 + q * 16, src);
        }
        cp_commit();
    };

    issue_chunk(0);
    if (nc > 1) issue_chunk(1);

    for (int c = 0; c < nc; c++) {
        if (c + 1 < nc) cp_wait<1>(); else cp_wait<0>();
        __syncthreads();
        if (c + 2 < nc) issue_chunk(c + 2);

        const uint32_t* Ah = sw + (c % NSTG) * STGW;
        const uint32_t* Al = Ah + TILEW;
        const uint32_t* Bh = Ah + 2*TILEW;
        const uint32_t* Bl = Ah + 3*TILEW;

        #pragma unroll
        for (int ks = 0; ks < 2; ks++) {
            const int kw = ks * 8 + t;
            uint32_t ah[4][4], al[4][4], bh[4][2], bl[4][2];
            #pragma unroll
            for (int mi = 0; mi < 4; mi++) {
                const int r = wm + mi * 16 + g;
                ah[mi][0] = Ah[r * PWW + kw];
                ah[mi][1] = Ah[(r + 8) * PWW + kw];
                ah[mi][2] = Ah[r * PWW + kw + 4];
                ah[mi][3] = Ah[(r + 8) * PWW + kw + 4];
                al[mi][0] = Al[r * PWW + kw];
                al[mi][1] = Al[(r + 8) * PWW + kw];
                al[mi][2] = Al[r * PWW + kw + 4];
                al[mi][3] = Al[(r + 8) * PWW + kw + 4];
            }
            #pragma unroll
            for (int nj = 0; nj < 4; nj++) {
                const int r = wn + nj * 8 + g;
                bh[nj][0] = Bh[r * PWW + kw];
                bh[nj][1] = Bh[r * PWW + kw + 4];
                bl[nj][0] = Bl[r * PWW + kw];
                bl[nj][1] = Bl[r * PWW + kw + 4];
            }
            #pragma unroll
            for (int mi = 0; mi < 4; mi++)
                #pragma unroll
                for (int nj = 0; nj < 4; nj++) {
                    mma_bf16(acc[mi][nj], ah[mi], bh[nj]);
                    mma_bf16(acc[mi][nj], ah[mi], bl[nj]);
                    mma_bf16(acc[mi][nj], al[mi], bh[nj]);
                }
        }
        __syncthreads();
    }

    #pragma unroll
    for (int mi = 0; mi < 4; mi++) {
        const int r0 = m0 + wm + mi * 16 + g;
        #pragma unroll
        for (int nj = 0; nj < 4; nj++) {
            const int cc = n0 + wn + nj * 8 + 2 * t;
            const float b0 = bias[cc], b1 = bias[cc + 1];
            float v0 = acc[mi][nj][0] + b0;
            float v1 = acc[mi][nj][1] + b1;
            float v2 = acc[mi][nj][2] + b0;
            float v3 = acc[mi][nj][3] + b1;
            if (SILU) {
                v0 = silu_f(v0); v1 = silu_f(v1);
                v2 = silu_f(v2); v3 = silu_f(v3);
            }
            *(float2*)&C[(size_t)r0 * N + cc]       = make_float2(v0, v1);
            *(float2*)&C[(size_t)(r0 + 8) * N + cc] = make_float2(v2, v3);
        }
    }
}

// ============================================================================
// HMMA flash attention (unchanged from R4, proven)
// ============================================================================
#define AQT 128
#define AKT 64
#define APW 36

#define QH_OFF 0
#define QL_OFF (128 * APW)
#define BUF_OFF (2 * 128 * APW)
#define BUF_W  (4 * 64 * APW)
#define KH_O 0
#define KL_O (64 * APW)
#define VTH_O (2 * 64 * APW)
#define VTL_O (3 * 64 * APW)
#define ASMEM_BYTES ((BUF_OFF + 2 * BUF_W) * 4)

__global__ __launch_bounds__(256)
void attn_hmma(const float* __restrict__ pos_w, float* __restrict__ y) {
    extern __shared__ __align__(16) uint32_t aw[];

    const int qt   = blockIdx.x;
    const int head = blockIdx.y;
    const int b    = blockIdx.z;
    const int tid  = threadIdx.x;
    const int wid  = tid >> 5;
    const int lane = tid & 31;
    const int g = lane >> 2, t = lane & 3;

    const size_t rs = FOURD;
    const float* ubase = g_h + (size_t)b * Ss * rs + 0*Dd + head * HDim;
    const float* qbase = g_h + (size_t)b * Ss * rs + 1*Dd + head * HDim;
    const float* kbase = g_h + (size_t)b * Ss * rs + 2*Dd + head * HDim;
    const float* vbase = g_h + (size_t)b * Ss * rs + 3*Dd + head * HDim;

    const int q_cta = qt * AQT;
    const int jtmax = 2 * qt + 1;

    #pragma unroll
    for (int it = 0; it < 8; it++) {
        int idx = it * 256 + tid;
        int r = idx >> 4, c = (idx & 15) * 4;
        float4 v = *(const float4*)&qbase[(size_t)(q_cta + r) * rs + c];
        float4 rem;
        uint2 h = cvt_hi(v, &rem);
        uint32_t wo = (uint32_t)(r * APW + c / 2);
        *(uint2*)(aw + QH_OFF + wo) = h;
        *(uint2*)(aw + QL_OFF + wo) = cvt_lo(rem);
    }

    float4 pk[4], pv[4];
    auto load_kv = [&](int jt) {
        const int k0 = jt * AKT;
        #pragma unroll
        for (int it = 0; it < 4; it++) {
            int idx = it * 256 + tid;
            int r = idx >> 4, c = (idx & 15) * 4;
            pk[it] = *(const float4*)&kbase[(size_t)(k0 + r) * rs + c];
            pv[it] = *(const float4*)&vbase[(size_t)(k0 + r) * rs + c];
        }
    };
    auto store_kv = [&](int buf) {
        uint32_t* base = aw + BUF_OFF + buf * BUF_W;
        __nv_bfloat16* vth = (__nv_bfloat16*)(base + VTH_O);
        __nv_bfloat16* vtl = (__nv_bfloat16*)(base + VTL_O);
        #pragma unroll
        for (int it = 0; it < 4; it++) {
            int idx = it * 256 + tid;
            int r = idx >> 4, c = (idx & 15) * 4;
            float4 rem;
            uint2 h = cvt_hi(pk[it], &rem);
            uint32_t wo = (uint32_t)(r * APW + c / 2);
            *(uint2*)(base + KH_O + wo) = h;
            *(uint2*)(base + KL_O + wo) = cvt_lo(rem);
            float vv[4] = {pv[it].x, pv[it].y, pv[it].z, pv[it].w};
            #pragma unroll
            for (int e = 0; e < 4; e++) {
                __nv_bfloat16 hi = __float2bfloat16(vv[e]);
                __nv_bfloat16 lo = __float2bfloat16(vv[e] - __bfloat162float(hi));
                vth[(c + e) * (2*APW) + r] = hi;
                vtl[(c + e) * (2*APW) + r] = lo;
            }
        }
    };

    load_kv(0);
    store_kv(0);
    __syncthreads();

    float O[8][4];
    #pragma unroll
    for (int nj = 0; nj < 8; nj++)
        #pragma unroll
        for (int e = 0; e < 4; e++) O[nj][e] = 0.f;

    const int q_warp = q_cta + wid * 16;
    const uint32_t* QHp = aw + QH_OFF;
    const uint32_t* QLp = aw + QL_OFF;

    for (int jt = 0; jt <= jtmax; jt++) {
        if (jt < jtmax) load_kv(jt + 1);

        const uint32_t* base = aw + BUF_OFF + (jt & 1) * BUF_W;
        const uint32_t* KHp  = base + KH_O;
        const uint32_t* KLp  = base + KL_O;
        const uint32_t* VHp  = base + VTH_O;
        const uint32_t* VLp  = base + VTL_O;

        if (jt * AKT <= q_warp + 15) {
            float S[8][4];
            #pragma unroll
            for (int nj = 0; nj < 8; nj++)
                #pragma unroll
                for (int e = 0; e < 4; e++) S[nj][e] = 0.f;

            #pragma unroll
            for (int ks = 0; ks < 4; ks++) {
                const int qa = (wid * 16 + g) * APW + ks * 8 + t;
                uint32_t ah[4], al[4];
                ah[0] = QHp[qa];           ah[1] = QHp[qa + 8*APW];
                ah[2] = QHp[qa + 4];       ah[3] = QHp[qa + 8*APW + 4];
                al[0] = QLp[qa];           al[1] = QLp[qa + 8*APW];
                al[2] = QLp[qa + 4];       al[3] = QLp[qa + 8*APW + 4];
                #pragma unroll
                for (int nj = 0; nj < 8; nj++) {
                    const int ka = (nj * 8 + g) * APW + ks * 8 + t;
                    uint32_t bh[2], bl[2];
                    bh[0] = KHp[ka]; bh[1] = KHp[ka + 4];
                    bl[0] = KLp[ka]; bl[1] = KLp[ka + 4];
                    mma_bf16(S[nj], ah, bh);
                    mma_bf16(S[nj], ah, bl);
                    mma_bf16(S[nj], al, bh);
                }
            }

            const int qg0 = q_warp + g;
            #pragma unroll
            for (int ks2 = 0; ks2 < 4; ks2++) {
                uint32_t ph[4], pl[4];
                #pragma unroll
                for (int half = 0; half < 2; half++) {
                    const float* sc = S[2*ks2 + half];
                    const int kc = jt * AKT + (2*ks2 + half) * 8 + 2*t;
                    float p00 = silu_f(sc[0] + pos_w[Mm - 1 + kc     - qg0]);
                    float p01 = silu_f(sc[1] + pos_w[Mm - 1 + kc + 1 - qg0]);
                    float p10 = silu_f(sc[2] + pos_w[Mm - 1 + kc     - (qg0+8)]);
                    float p11 = silu_f(sc[3] + pos_w[Mm - 1 + kc + 1 - (qg0+8)]);
                    if (kc     > qg0)   p00 = 0.f;
                    if (kc + 1 > qg0)   p01 = 0.f;
                    if (kc     > qg0+8) p10 = 0.f;
                    if (kc + 1 > qg0+8) p11 = 0.f;
                    __nv_bfloat16 h00 = __float2bfloat16(p00);
                    __nv_bfloat16 h01 = __float2bfloat16(p01);
                    __nv_bfloat16 h10 = __float2bfloat16(p10);
                    __nv_bfloat16 h11 = __float2bfloat16(p11);
                    __nv_bfloat162 hp0(h00, h01), hp1(h10, h11);
                    __nv_bfloat162 lp0(__float2bfloat16(p00 - __bfloat162float(h00)),
                                       __float2bfloat16(p01 - __bfloat162float(h01)));
                    __nv_bfloat162 lp1(__float2bfloat16(p10 - __bfloat162float(h10)),
                                       __float2bfloat16(p11 - __bfloat162float(h11)));
                    ph[0 + half*2] = *(uint32_t*)&hp0;
                    ph[1 + half*2] = *(uint32_t*)&hp1;
                    pl[0 + half*2] = *(uint32_t*)&lp0;
                    pl[1 + half*2] = *(uint32_t*)&lp1;
                }
                #pragma unroll
                for (int nj = 0; nj < 8; nj++) {
                    const int va = (nj * 8 + g) * APW + ks2 * 8 + t;
                    uint32_t vh[2], vl[2];
                    vh[0] = VHp[va]; vh[1] = VHp[va + 4];
                    vl[0] = VLp[va]; vl[1] = VLp[va + 4];
                    mma_bf16(O[nj], ph, vh);
                    mma_bf16(O[nj], ph, vl);
                    mma_bf16(O[nj], pl, vh);
                }
            }
        }

        if (jt < jtmax) {
            store_kv((jt + 1) & 1);
            __syncthreads();
        }
    }

    #pragma unroll
    for (int nj = 0; nj < 8; nj++) {
        const int d = nj * 8 + 2 * t;
        #pragma unroll
        for (int half = 0; half < 2; half++) {
            const int q = q_warp + g + half * 8;
            const float2 u = *(const float2*)&ubase[(size_t)q * rs + d];
            float2 r;
            r.x = O[nj][half*2 + 0] * u.x;
            r.y = O[nj][half*2 + 1] * u.y;
            *(float2*)&y[((size_t)b * Ss + q) * Dd + head * HDim + d] = r;
        }
    }
}

// ---------------- LayerNorm (fp32 or bf16-hi/lo output) ------------------------
__device__ __forceinline__ float block_sum(float v, float* sbuf) {
    #pragma unroll
    for (int o = 16; o > 0; o >>= 1) v += __shfl_down_sync(0xffffffffu, v, o);
    const int lane = threadIdx.x & 31, w = threadIdx.x >> 5;
    if (lane == 0) sbuf[w] = v;
    __syncthreads();
    if (w == 0) {
        v = (lane < 8) ? sbuf[lane] : 0.f;
        #pragma unroll
        for (int o = 4; o > 0; o >>= 1) v += __shfl_down_sync(0xffffffffu, v, o);
        if (lane == 0) sbuf[0] = v;
    }
    __syncthreads();
    float r = sbuf[0];
    __syncthreads();
    return r;
}

template<bool BF16OUT>
__global__ __launch_bounds__(256)
void ln_kernel(const float* __restrict__ in, const float* __restrict__ res,
               const float* __restrict__ g, const float* __restrict__ beta,
               float* __restrict__ out,
               __nv_bfloat16* __restrict__ outh, __nv_bfloat16* __restrict__ outl) {
    __shared__ float sbuf[8];
    const size_t row = blockIdx.x;
    const int c = threadIdx.x * 4;
    float4 v = *(const float4*)&in[row * Dd + c];
    if (res) {
        float4 r = *(const float4*)&res[row * Dd + c];
        v.x += r.x; v.y += r.y; v.z += r.z; v.w += r.w;
    }
    const float total = block_sum(v.x + v.y + v.z + v.w, sbuf);
    const float mu = total * (1.f / Dd);
    float dx = v.x - mu, dy = v.y - mu, dz = v.z - mu, dw = v.w - mu;
    const float ssq = block_sum(dx*dx + dy*dy + dz*dz + dw*dw, sbuf);
    const float inv = rsqrtf(ssq * (1.f / Dd) + EPS);
    float4 gv = *(const float4*)&g[c];
    float4 bv = *(const float4*)&beta[c];
    float4 r;
    r.x = dx * inv * gv.x + bv.x;
    r.y = dy * inv * gv.y + bv.y;
    r.z = dz * inv * gv.z + bv.z;
    r.w = dw * inv * gv.w + bv.w;
    if (BF16OUT) {
        float4 rem;
        uint2 h = cvt_hi(r, &rem);
        *(uint2*)&outh[row * Dd + c] = h;
        *(uint2*)&outl[row * Dd + c] = cvt_lo(rem);
    } else {
        *(float4*)&out[row * Dd + c] = r;
    }
}

// ---------------- launch ------------------------------------------------------
extern "C" void kernel_launch(void* const* d_in, const int* in_sizes, int n_in,
                              void* d_out, int out_size) {
    const float* x     = (const float*)d_in[0];
    const float* w1    = (const float*)d_in[2];
    const float* b1    = (const float*)d_in[3];
    const float* w2    = (const float*)d_in[4];
    const float* b2    = (const float*)d_in[5];
    const float* g1    = (const float*)d_in[6];
    const float* beta1 = (const float*)d_in[7];
    const float* g2    = (const float*)d_in[8];
    const float* beta2 = (const float*)d_in[9];
    const float* pos_w = (const float*)d_in[10];
    float* out = (float*)d_out;

    float *hbuf, *ybuf, *tbuf;
    __nv_bfloat16 *xh, *xl, *w1h, *w1l, *w2h, *w2l, *zh, *zl;
    cudaGetSymbolAddress((void**)&hbuf, g_h);
    cudaGetSymbolAddress((void**)&ybuf, g_y);
    cudaGetSymbolAddress((void**)&tbuf, g_t);
    cudaGetSymbolAddress((void**)&xh,  g_xh);  cudaGetSymbolAddress((void**)&xl,  g_xl);
    cudaGetSymbolAddress((void**)&w1h, g_w1h); cudaGetSymbolAddress((void**)&w1l, g_w1l);
    cudaGetSymbolAddress((void**)&w2h, g_w2h); cudaGetSymbolAddress((void**)&w2l, g_w2l);
    cudaGetSymbolAddress((void**)&zh,  g_zh);  cudaGetSymbolAddress((void**)&zl,  g_zl);

    cudaFuncSetAttribute(hmma_gemm_cp<true>,  cudaFuncAttributeMaxDynamicSharedMemorySize, GSMEM_BYTES);
    cudaFuncSetAttribute(hmma_gemm_cp<false>, cudaFuncAttributeMaxDynamicSharedMemorySize, GSMEM_BYTES);
    cudaFuncSetAttribute(attn_hmma, cudaFuncAttributeMaxDynamicSharedMemorySize, ASMEM_BYTES);

    // 0) pre-convert x, w1, w2 to bf16 hi/lo
    cvt_kernel<<<1024, 256>>>(x,  xh,  xl,  NTOK  * Dd / 4);
    cvt_kernel<<<1024, 256>>>(w1, w1h, w1l, FOURD * Dd / 4);
    cvt_kernel<<<1024, 256>>>(w2, w2h, w2l, Dd    * Dd / 4);

    // 1) h = silu(x @ w1^T + b1)
    hmma_gemm_cp<true><<<dim3(FOURD/BN, NTOK/BM), 256, GSMEM_BYTES>>>(
        xh, xl, w1h, w1l, b1, hbuf, FOURD, Dd);

    // 2) fused HMMA attention + u gate -> g_y
    attn_hmma<<<dim3(Ss/AQT, Hh, Bb), 256, ASMEM_BYTES>>>(pos_w, ybuf);

    // 3) LN1 -> z (bf16 hi/lo)
    ln_kernel<true><<<NTOK, 256>>>(ybuf, nullptr, g1, beta1, nullptr, zh, zl);

    // 4) t = z @ w2^T + b2
    hmma_gemm_cp<false><<<dim3(Dd/BN, NTOK/BM), 256, GSMEM_BYTES>>>(
        zh, zl, w2h, w2l, b2, tbuf, Dd, Dd);

    // 5) out = LN(t + x)
    ln_kernel<false><<<NTOK, 256>>>(tbuf, x, g2, beta2, out, nullptr, nullptr);
}

// round 6
// speedup vs baseline: 1.9340x; 1.0674x over previous
#include <cuda_runtime.h>
#include <cuda_bf16.h>
#include <cstdint>
#include <cstddef>

// Problem constants
#define Bb 2
#define Ss 2048
#define Dd 1024
#define Hh 16
#define HDim 64
#define Mm 4096
#define NTOK (Bb*Ss)          // 4096
#define FOURD (4*Dd)          // 4096
#define EPS 1e-5f

// ---------------- scratch ----------------------------------------------------
__device__ float g_h[(size_t)NTOK * FOURD];   // silu(x@w1^T+b1)
__device__ float g_y[(size_t)NTOK * Dd];      // gated attention out
__device__ float g_t[(size_t)NTOK * Dd];      // GEMM2 out
// bf16 hi/lo pre-converted operands
__device__ __nv_bfloat16 g_xh[(size_t)NTOK * Dd],  g_xl[(size_t)NTOK * Dd];
__device__ __nv_bfloat16 g_w1h[(size_t)FOURD * Dd], g_w1l[(size_t)FOURD * Dd];
__device__ __nv_bfloat16 g_w2h[(size_t)Dd * Dd],   g_w2l[(size_t)Dd * Dd];
__device__ __nv_bfloat16 g_zh[(size_t)NTOK * Dd],  g_zl[(size_t)NTOK * Dd];

// ---------------- common helpers ----------------------------------------------
__device__ __forceinline__ void mma_bf16(float* c, const uint32_t* a, const uint32_t* b) {
    asm volatile(
        "mma.sync.aligned.m16n8k16.row.col.f32.bf16.bf16.f32 "
        "{%0,%1,%2,%3}, {%4,%5,%6,%7}, {%8,%9}, {%0,%1,%2,%3};"
        : "+f"(c[0]), "+f"(c[1]), "+f"(c[2]), "+f"(c[3])
        : "r"(a[0]), "r"(a[1]), "r"(a[2]), "r"(a[3]), "r"(b[0]), "r"(b[1]));
}
__device__ __forceinline__ uint2 cvt_hi(float4 g, float4* rem) {
    __nv_bfloat16 h0 = __float2bfloat16(g.x), h1 = __float2bfloat16(g.y);
    __nv_bfloat16 h2 = __float2bfloat16(g.z), h3 = __float2bfloat16(g.w);
    rem->x = g.x - __bfloat162float(h0);
    rem->y = g.y - __bfloat162float(h1);
    rem->z = g.z - __bfloat162float(h2);
    rem->w = g.w - __bfloat162float(h3);
    __nv_bfloat162 p0(h0, h1), p1(h2, h3);
    return make_uint2(*(uint32_t*)&p0, *(uint32_t*)&p1);
}
__device__ __forceinline__ uint2 cvt_lo(float4 g) {
    __nv_bfloat16 l0 = __float2bfloat16(g.x), l1 = __float2bfloat16(g.y);
    __nv_bfloat16 l2 = __float2bfloat16(g.z), l3 = __float2bfloat16(g.w);
    __nv_bfloat162 p0(l0, l1), p1(l2, l3);
    return make_uint2(*(uint32_t*)&p0, *(uint32_t*)&p1);
}
__device__ __forceinline__ float silu_f(float v) {
    return v / (1.f + __expf(-v));
}
__device__ __forceinline__ uint32_t smem_u32(const void* p) {
    uint32_t a;
    asm("{ .reg .u64 t; cvta.to.shared.u64 t, %1; cvt.u32.u64 %0, t; }"
        : "=r"(a) : "l"(p));
    return a;
}
__device__ __forceinline__ void cp16(uint32_t dst, const void* src) {
    asm volatile("cp.async.cg.shared.global [%0], [%1], 16;" :: "r"(dst), "l"(src));
}
__device__ __forceinline__ void cp_commit() {
    asm volatile("cp.async.commit_group;" ::: "memory");
}
template<int N>
__device__ __forceinline__ void cp_wait() {
    asm volatile("cp.async.wait_group %0;" :: "n"(N) : "memory");
}

// ---------------- fp32 -> bf16 hi/lo converter ---------------------------------
__global__ __launch_bounds__(256)
void cvt_kernel(const float* __restrict__ in, __nv_bfloat16* __restrict__ hi,
                __nv_bfloat16* __restrict__ lo, int n4) {
    for (int i = blockIdx.x * 256 + threadIdx.x; i < n4; i += gridDim.x * 256) {
        float4 v = *(const float4*)&in[i * 4];
        float4 rem;
        uint2 h = cvt_hi(v, &rem);
        *(uint2*)&hi[i * 4] = h;
        *(uint2*)&lo[i * 4] = cvt_lo(rem);
    }
}

// ============================================================================
// bf16 hi/lo HMMA GEMM, cp.async 2-stage pipeline, 2 CTAs/SM
// ============================================================================
#define BM 128
#define BN 128
#define KC 32
#define PWW 20                         // SMEM row pitch in words (80 B)
#define TILEW (128 * PWW)              // words per tile (10240 B)
#define STGW  (4 * TILEW)              // words per stage (Ah,Al,Bh,Bl) 40960 B
#define NSTG 2
#define GSMEM_BYTES (NSTG * STGW * 4)  // 81920

template<bool SILU>
__global__ __launch_bounds__(256, 2)
void hmma_gemm_cp(const __nv_bfloat16* __restrict__ Ahg, const __nv_bfloat16* __restrict__ Alg,
                  const __nv_bfloat16* __restrict__ Bhg, const __nv_bfloat16* __restrict__ Blg,
                  const float* __restrict__ bias, float* __restrict__ C,
                  int N, int K) {
    extern __shared__ __align__(16) uint32_t sw[];
    const uint32_t smb = smem_u32(sw);
    const int tid  = threadIdx.x;
    const int wid  = tid >> 5;
    const int lane = tid & 31;
    const int g = lane >> 2, t = lane & 3;
    const int m0 = blockIdx.y * BM;
    const int n0 = blockIdx.x * BN;
    const int wm = (wid >> 2) * 64;
    const int wn = (wid & 3) * 32;

    const __nv_bfloat16* tp[4] = {Ahg, Alg, Bhg, Blg};

    float acc[4][4][4];
    #pragma unroll
    for (int i = 0; i < 4; i++)
        #pragma unroll
        for (int j = 0; j < 4; j++)
            #pragma unroll
            for (int e = 0; e < 4; e++) acc[i][j][e] = 0.f;

    const int nc = K / KC;

    auto issue_chunk = [&](int c) {
        const int k0 = c * KC;
        const uint32_t stg_b = smb + (c & 1) * (STGW * 4);
        #pragma unroll
        for (int it = 0; it < 8; it++) {
            int idx = it * 256 + tid;          // 0..2047 16B ops
            int tile = idx >> 9;               // 0..3
            int r = (idx >> 2) & 127;
            int q = idx & 3;
            int row = (tile < 2 ? m0 : n0) + r;
            const __nv_bfloat16* src = tp[tile] + (size_t)row * K + k0 + q * 8;
            cp16(stg_b + tile * (TILEW * 4) + r * 80 + q * 16, src);
        }
        cp_commit();
    };

    issue_chunk(0);

    for (int c = 0; c < nc; c++) {
        cp_wait<0>();
        __syncthreads();
        if (c + 1 < nc) issue_chunk(c + 1);   // overlaps with compute below

        const uint32_t* Ah = sw + (c & 1) * STGW;
        const uint32_t* Al = Ah + TILEW;
        const uint32_t* Bh = Ah + 2*TILEW;
        const uint32_t* Bl = Ah + 3*TILEW;

        #pragma unroll
        for (int ks = 0; ks < 2; ks++) {
            const int kw = ks * 8 + t;
            uint32_t ah[4][4], al[4][4], bh[4][2], bl[4][2];
            #pragma unroll
            for (int mi = 0; mi < 4; mi++) {
                const int r = wm + mi * 16 + g;
                ah[mi][0] = Ah[r * PWW + kw];
                ah[mi][1] = Ah[(r + 8) * PWW + kw];
                ah[mi][2] = Ah[r * PWW + kw + 4];
                ah[mi][3] = Ah[(r + 8) * PWW + kw + 4];
                al[mi][0] = Al[r * PWW + kw];
                al[mi][1] = Al[(r + 8) * PWW + kw];
                al[mi][2] = Al[r * PWW + kw + 4];
                al[mi][3] = Al[(r + 8) * PWW + kw + 4];
            }
            #pragma unroll
            for (int nj = 0; nj < 4; nj++) {
                const int r = wn + nj * 8 + g;
                bh[nj][0] = Bh[r * PWW + kw];
                bh[nj][1] = Bh[r * PWW + kw + 4];
                bl[nj][0] = Bl[r * PWW + kw];
                bl[nj][1] = Bl[r * PWW + kw + 4];
            }
            #pragma unroll
            for (int mi = 0; mi < 4; mi++)
                #pragma unroll
                for (int nj = 0; nj < 4; nj++) {
                    mma_bf16(acc[mi][nj], ah[mi], bh[nj]);
                    mma_bf16(acc[mi][nj], ah[mi], bl[nj]);
                    mma_bf16(acc[mi][nj], al[mi], bh[nj]);
                }
        }
    }

    #pragma unroll
    for (int mi = 0; mi < 4; mi++) {
        const int r0 = m0 + wm + mi * 16 + g;
        #pragma unroll
        for (int nj = 0; nj < 4; nj++) {
            const int cc = n0 + wn + nj * 8 + 2 * t;
            const float b0 = bias[cc], b1 = bias[cc + 1];
            float v0 = acc[mi][nj][0] + b0;
            float v1 = acc[mi][nj][1] + b1;
            float v2 = acc[mi][nj][2] + b0;
            float v3 = acc[mi][nj][3] + b1;
            if (SILU) {
                v0 = silu_f(v0); v1 = silu_f(v1);
                v2 = silu_f(v2); v3 = silu_f(v3);
            }
            *(float2*)&C[(size_t)r0 * N + cc]       = make_float2(v0, v1);
            *(float2*)&C[(size_t)(r0 + 8) * N + cc] = make_float2(v2, v3);
        }
    }
}

// ============================================================================
// HMMA flash attention (unchanged, proven)
// ============================================================================
#define AQT 128
#define AKT 64
#define APW 36

#define QH_OFF 0
#define QL_OFF (128 * APW)
#define BUF_OFF (2 * 128 * APW)
#define BUF_W  (4 * 64 * APW)
#define KH_O 0
#define KL_O (64 * APW)
#define VTH_O (2 * 64 * APW)
#define VTL_O (3 * 64 * APW)
#define ASMEM_BYTES ((BUF_OFF + 2 * BUF_W) * 4)

__global__ __launch_bounds__(256)
void attn_hmma(const float* __restrict__ pos_w, float* __restrict__ y) {
    extern __shared__ __align__(16) uint32_t aw[];

    const int qt   = blockIdx.x;
    const int head = blockIdx.y;
    const int b    = blockIdx.z;
    const int tid  = threadIdx.x;
    const int wid  = tid >> 5;
    const int lane = tid & 31;
    const int g = lane >> 2, t = lane & 3;

    const size_t rs = FOURD;
    const float* ubase = g_h + (size_t)b * Ss * rs + 0*Dd + head * HDim;
    const float* qbase = g_h + (size_t)b * Ss * rs + 1*Dd + head * HDim;
    const float* kbase = g_h + (size_t)b * Ss * rs + 2*Dd + head * HDim;
    const float* vbase = g_h + (size_t)b * Ss * rs + 3*Dd + head * HDim;

    const int q_cta = qt * AQT;
    const int jtmax = 2 * qt + 1;

    #pragma unroll
    for (int it = 0; it < 8; it++) {
        int idx = it * 256 + tid;
        int r = idx >> 4, c = (idx & 15) * 4;
        float4 v = *(const float4*)&qbase[(size_t)(q_cta + r) * rs + c];
        float4 rem;
        uint2 h = cvt_hi(v, &rem);
        uint32_t wo = (uint32_t)(r * APW + c / 2);
        *(uint2*)(aw + QH_OFF + wo) = h;
        *(uint2*)(aw + QL_OFF + wo) = cvt_lo(rem);
    }

    float4 pk[4], pv[4];
    auto load_kv = [&](int jt) {
        const int k0 = jt * AKT;
        #pragma unroll
        for (int it = 0; it < 4; it++) {
            int idx = it * 256 + tid;
            int r = idx >> 4, c = (idx & 15) * 4;
            pk[it] = *(const float4*)&kbase[(size_t)(k0 + r) * rs + c];
            pv[it] = *(const float4*)&vbase[(size_t)(k0 + r) * rs + c];
        }
    };
    auto store_kv = [&](int buf) {
        uint32_t* base = aw + BUF_OFF + buf * BUF_W;
        __nv_bfloat16* vth = (__nv_bfloat16*)(base + VTH_O);
        __nv_bfloat16* vtl = (__nv_bfloat16*)(base + VTL_O);
        #pragma unroll
        for (int it = 0; it < 4; it++) {
            int idx = it * 256 + tid;
            int r = idx >> 4, c = (idx & 15) * 4;
            float4 rem;
            uint2 h = cvt_hi(pk[it], &rem);
            uint32_t wo = (uint32_t)(r * APW + c / 2);
            *(uint2*)(base + KH_O + wo) = h;
            *(uint2*)(base + KL_O + wo) = cvt_lo(rem);
            float vv[4] = {pv[it].x, pv[it].y, pv[it].z, pv[it].w};
            #pragma unroll
            for (int e = 0; e < 4; e++) {
                __nv_bfloat16 hi = __float2bfloat16(vv[e]);
                __nv_bfloat16 lo = __float2bfloat16(vv[e] - __bfloat162float(hi));
                vth[(c + e) * (2*APW) + r] = hi;
                vtl[(c + e) * (2*APW) + r] = lo;
            }
        }
    };

    load_kv(0);
    store_kv(0);
    __syncthreads();

    float O[8][4];
    #pragma unroll
    for (int nj = 0; nj < 8; nj++)
        #pragma unroll
        for (int e = 0; e < 4; e++) O[nj][e] = 0.f;

    const int q_warp = q_cta + wid * 16;
    const uint32_t* QHp = aw + QH_OFF;
    const uint32_t* QLp = aw + QL_OFF;

    for (int jt = 0; jt <= jtmax; jt++) {
        if (jt < jtmax) load_kv(jt + 1);

        const uint32_t* base = aw + BUF_OFF + (jt & 1) * BUF_W;
        const uint32_t* KHp  = base + KH_O;
        const uint32_t* KLp  = base + KL_O;
        const uint32_t* VHp  = base + VTH_O;
        const uint32_t* VLp  = base + VTL_O;

        if (jt * AKT <= q_warp + 15) {
            float S[8][4];
            #pragma unroll
            for (int nj = 0; nj < 8; nj++)
                #pragma unroll
                for (int e = 0; e < 4; e++) S[nj][e] = 0.f;

            #pragma unroll
            for (int ks = 0; ks < 4; ks++) {
                const int qa = (wid * 16 + g) * APW + ks * 8 + t;
                uint32_t ah[4], al[4];
                ah[0] = QHp[qa];           ah[1] = QHp[qa + 8*APW];
                ah[2] = QHp[qa + 4];       ah[3] = QHp[qa + 8*APW + 4];
                al[0] = QLp[qa];           al[1] = QLp[qa + 8*APW];
                al[2] = QLp[qa + 4];       al[3] = QLp[qa + 8*APW + 4];
                #pragma unroll
                for (int nj = 0; nj < 8; nj++) {
                    const int ka = (nj * 8 + g) * APW + ks * 8 + t;
                    uint32_t bh[2], bl[2];
                    bh[0] = KHp[ka]; bh[1] = KHp[ka + 4];
                    bl[0] = KLp[ka]; bl[1] = KLp[ka + 4];
                    mma_bf16(S[nj], ah, bh);
                    mma_bf16(S[nj], ah, bl);
                    mma_bf16(S[nj], al, bh);
                }
            }

            const int qg0 = q_warp + g;
            #pragma unroll
            for (int ks2 = 0; ks2 < 4; ks2++) {
                uint32_t ph[4], pl[4];
                #pragma unroll
                for (int half = 0; half < 2; half++) {
                    const float* sc = S[2*ks2 + half];
                    const int kc = jt * AKT + (2*ks2 + half) * 8 + 2*t;
                    float p00 = silu_f(sc[0] + pos_w[Mm - 1 + kc     - qg0]);
                    float p01 = silu_f(sc[1] + pos_w[Mm - 1 + kc + 1 - qg0]);
                    float p10 = silu_f(sc[2] + pos_w[Mm - 1 + kc     - (qg0+8)]);
                    float p11 = silu_f(sc[3] + pos_w[Mm - 1 + kc + 1 - (qg0+8)]);
                    if (kc     > qg0)   p00 = 0.f;
                    if (kc + 1 > qg0)   p01 = 0.f;
                    if (kc     > qg0+8) p10 = 0.f;
                    if (kc + 1 > qg0+8) p11 = 0.f;
                    __nv_bfloat16 h00 = __float2bfloat16(p00);
                    __nv_bfloat16 h01 = __float2bfloat16(p01);
                    __nv_bfloat16 h10 = __float2bfloat16(p10);
                    __nv_bfloat16 h11 = __float2bfloat16(p11);
                    __nv_bfloat162 hp0(h00, h01), hp1(h10, h11);
                    __nv_bfloat162 lp0(__float2bfloat16(p00 - __bfloat162float(h00)),
                                       __float2bfloat16(p01 - __bfloat162float(h01)));
                    __nv_bfloat162 lp1(__float2bfloat16(p10 - __bfloat162float(h10)),
                                       __float2bfloat16(p11 - __bfloat162float(h11)));
                    ph[0 + half*2] = *(uint32_t*)&hp0;
                    ph[1 + half*2] = *(uint32_t*)&hp1;
                    pl[0 + half*2] = *(uint32_t*)&lp0;
                    pl[1 + half*2] = *(uint32_t*)&lp1;
                }
                #pragma unroll
                for (int nj = 0; nj < 8; nj++) {
                    const int va = (nj * 8 + g) * APW + ks2 * 8 + t;
                    uint32_t vh[2], vl[2];
                    vh[0] = VHp[va]; vh[1] = VHp[va + 4];
                    vl[0] = VLp[va]; vl[1] = VLp[va + 4];
                    mma_bf16(O[nj], ph, vh);
                    mma_bf16(O[nj], ph, vl);
                    mma_bf16(O[nj], pl, vh);
                }
            }
        }

        if (jt < jtmax) {
            store_kv((jt + 1) & 1);
            __syncthreads();
        }
    }

    #pragma unroll
    for (int nj = 0; nj < 8; nj++) {
        const int d = nj * 8 + 2 * t;
        #pragma unroll
        for (int half = 0; half < 2; half++) {
            const int q = q_warp + g + half * 8;
            const float2 u = *(const float2*)&ubase[(size_t)q * rs + d];
            float2 r;
            r.x = O[nj][half*2 + 0] * u.x;
            r.y = O[nj][half*2 + 1] * u.y;
            *(float2*)&y[((size_t)b * Ss + q) * Dd + head * HDim + d] = r;
        }
    }
}

// ---------------- LayerNorm (fp32 or bf16-hi/lo output) ------------------------
__device__ __forceinline__ float block_sum(float v, float* sbuf) {
    #pragma unroll
    for (int o = 16; o > 0; o >>= 1) v += __shfl_down_sync(0xffffffffu, v, o);
    const int lane = threadIdx.x & 31, w = threadIdx.x >> 5;
    if (lane == 0) sbuf[w] = v;
    __syncthreads();
    if (w == 0) {
        v = (lane < 8) ? sbuf[lane] : 0.f;
        #pragma unroll
        for (int o = 4; o > 0; o >>= 1) v += __shfl_down_sync(0xffffffffu, v, o);
        if (lane == 0) sbuf[0] = v;
    }
    __syncthreads();
    float r = sbuf[0];
    __syncthreads();
    return r;
}

template<bool BF16OUT>
__global__ __launch_bounds__(256)
void ln_kernel(const float* __restrict__ in, const float* __restrict__ res,
               const float* __restrict__ g, const float* __restrict__ beta,
               float* __restrict__ out,
               __nv_bfloat16* __restrict__ outh, __nv_bfloat16* __restrict__ outl) {
    __shared__ float sbuf[8];
    const size_t row = blockIdx.x;
    const int c = threadIdx.x * 4;
    float4 v = *(const float4*)&in[row * Dd + c];
    if (res) {
        float4 r = *(const float4*)&res[row * Dd + c];
        v.x += r.x; v.y += r.y; v.z += r.z; v.w += r.w;
    }
    const float total = block_sum(v.x + v.y + v.z + v.w, sbuf);
    const float mu = total * (1.f / Dd);
    float dx = v.x - mu, dy = v.y - mu, dz = v.z - mu, dw = v.w - mu;
    const float ssq = block_sum(dx*dx + dy*dy + dz*dz + dw*dw, sbuf);
    const float inv = rsqrtf(ssq * (1.f / Dd) + EPS);
    float4 gv = *(const float4*)&g[c];
    float4 bv = *(const float4*)&beta[c];
    float4 r;
    r.x = dx * inv * gv.x + bv.x;
    r.y = dy * inv * gv.y + bv.y;
    r.z = dz * inv * gv.z + bv.z;
    r.w = dw * inv * gv.w + bv.w;
    if (BF16OUT) {
        float4 rem;
        uint2 h = cvt_hi(r, &rem);
        *(uint2*)&outh[row * Dd + c] = h;
        *(uint2*)&outl[row * Dd + c] = cvt_lo(rem);
    } else {
        *(float4*)&out[row * Dd + c] = r;
    }
}

// ---------------- launch ------------------------------------------------------
extern "C" void kernel_launch(void* const* d_in, const int* in_sizes, int n_in,
                              void* d_out, int out_size) {
    const float* x     = (const float*)d_in[0];
    const float* w1    = (const float*)d_in[2];
    const float* b1    = (const float*)d_in[3];
    const float* w2    = (const float*)d_in[4];
    const float* b2    = (const float*)d_in[5];
    const float* g1    = (const float*)d_in[6];
    const float* beta1 = (const float*)d_in[7];
    const float* g2    = (const float*)d_in[8];
    const float* beta2 = (const float*)d_in[9];
    const float* pos_w = (const float*)d_in[10];
    float* out = (float*)d_out;

    float *hbuf, *ybuf, *tbuf;
    __nv_bfloat16 *xh, *xl, *w1h, *w1l, *w2h, *w2l, *zh, *zl;
    cudaGetSymbolAddress((void**)&hbuf, g_h);
    cudaGetSymbolAddress((void**)&ybuf, g_y);
    cudaGetSymbolAddress((void**)&tbuf, g_t);
    cudaGetSymbolAddress((void**)&xh,  g_xh);  cudaGetSymbolAddress((void**)&xl,  g_xl);
    cudaGetSymbolAddress((void**)&w1h, g_w1h); cudaGetSymbolAddress((void**)&w1l, g_w1l);
    cudaGetSymbolAddress((void**)&w2h, g_w2h); cudaGetSymbolAddress((void**)&w2l, g_w2l);
    cudaGetSymbolAddress((void**)&zh,  g_zh);  cudaGetSymbolAddress((void**)&zl,  g_zl);

    cudaFuncSetAttribute(hmma_gemm_cp<true>,  cudaFuncAttributeMaxDynamicSharedMemorySize, GSMEM_BYTES);
    cudaFuncSetAttribute(hmma_gemm_cp<false>, cudaFuncAttributeMaxDynamicSharedMemorySize, GSMEM_BYTES);
    cudaFuncSetAttribute(attn_hmma, cudaFuncAttributeMaxDynamicSharedMemorySize, ASMEM_BYTES);

    // 0) pre-convert x, w1, w2 to bf16 hi/lo
    cvt_kernel<<<1024, 256>>>(x,  xh,  xl,  NTOK  * Dd / 4);
    cvt_kernel<<<1024, 256>>>(w1, w1h, w1l, FOURD * Dd / 4);
    cvt_kernel<<<1024, 256>>>(w2, w2h, w2l, Dd    * Dd / 4);

    // 1) h = silu(x @ w1^T + b1)
    hmma_gemm_cp<true><<<dim3(FOURD/BN, NTOK/BM), 256, GSMEM_BYTES>>>(
        xh, xl, w1h, w1l, b1, hbuf, FOURD, Dd);

    // 2) fused HMMA attention + u gate -> g_y
    attn_hmma<<<dim3(Ss/AQT, Hh, Bb), 256, ASMEM_BYTES>>>(pos_w, ybuf);

    // 3) LN1 -> z (bf16 hi/lo)
    ln_kernel<true><<<NTOK, 256>>>(ybuf, nullptr, g1, beta1, nullptr, zh, zl);

    // 4) t = z @ w2^T + b2
    hmma_gemm_cp<false><<<dim3(Dd/BN, NTOK/BM), 256, GSMEM_BYTES>>>(
        zh, zl, w2h, w2l, b2, tbuf, Dd, Dd);

    // 5) out = LN(t + x)
    ln_kernel<false><<<NTOK, 256>>>(tbuf, x, g2, beta2, out, nullptr, nullptr);
}

// round 7
// speedup vs baseline: 2.1279x; 1.1003x over previous
#include <cuda_runtime.h>
#include <cuda_bf16.h>
#include <cstdint>
#include <cstddef>

// Problem constants
#define Bb 2
#define Ss 2048
#define Dd 1024
#define Hh 16
#define HDim 64
#define Mm 4096
#define NTOK (Bb*Ss)          // 4096
#define FOURD (4*Dd)          // 4096
#define EPS 1e-5f

// ---------------- scratch ----------------------------------------------------
__device__ float g_h[(size_t)NTOK * FOURD];   // silu(x@w1^T+b1)
__device__ float g_y[(size_t)NTOK * Dd];      // gated attention out
__device__ float g_t[(size_t)NTOK * Dd];      // GEMM2 out
// bf16 hi/lo pre-converted operands
__device__ __nv_bfloat16 g_xh[(size_t)NTOK * Dd],  g_xl[(size_t)NTOK * Dd];
__device__ __nv_bfloat16 g_w1h[(size_t)FOURD * Dd], g_w1l[(size_t)FOURD * Dd];
__device__ __nv_bfloat16 g_w2h[(size_t)Dd * Dd],   g_w2l[(size_t)Dd * Dd];
__device__ __nv_bfloat16 g_zh[(size_t)NTOK * Dd],  g_zl[(size_t)NTOK * Dd];

// ---------------- common helpers ----------------------------------------------
__device__ __forceinline__ void mma_bf16(float* c, const uint32_t* a, const uint32_t* b) {
    asm volatile(
        "mma.sync.aligned.m16n8k16.row.col.f32.bf16.bf16.f32 "
        "{%0,%1,%2,%3}, {%4,%5,%6,%7}, {%8,%9}, {%0,%1,%2,%3};"
        : "+f"(c[0]), "+f"(c[1]), "+f"(c[2]), "+f"(c[3])
        : "r"(a[0]), "r"(a[1]), "r"(a[2]), "r"(a[3]), "r"(b[0]), "r"(b[1]));
}
__device__ __forceinline__ void ldm_x4(uint32_t* r, uint32_t addr) {
    asm volatile("ldmatrix.sync.aligned.m8n8.x4.shared.b16 {%0,%1,%2,%3}, [%4];"
        : "=r"(r[0]), "=r"(r[1]), "=r"(r[2]), "=r"(r[3]) : "r"(addr));
}
__device__ __forceinline__ uint2 cvt_hi(float4 g, float4* rem) {
    __nv_bfloat16 h0 = __float2bfloat16(g.x), h1 = __float2bfloat16(g.y);
    __nv_bfloat16 h2 = __float2bfloat16(g.z), h3 = __float2bfloat16(g.w);
    rem->x = g.x - __bfloat162float(h0);
    rem->y = g.y - __bfloat162float(h1);
    rem->z = g.z - __bfloat162float(h2);
    rem->w = g.w - __bfloat162float(h3);
    __nv_bfloat162 p0(h0, h1), p1(h2, h3);
    return make_uint2(*(uint32_t*)&p0, *(uint32_t*)&p1);
}
__device__ __forceinline__ uint2 cvt_lo(float4 g) {
    __nv_bfloat16 l0 = __float2bfloat16(g.x), l1 = __float2bfloat16(g.y);
    __nv_bfloat16 l2 = __float2bfloat16(g.z), l3 = __float2bfloat16(g.w);
    __nv_bfloat162 p0(l0, l1), p1(l2, l3);
    return make_uint2(*(uint32_t*)&p0, *(uint32_t*)&p1);
}
__device__ __forceinline__ float silu_f(float v) {
    return v / (1.f + __expf(-v));
}
__device__ __forceinline__ uint32_t smem_u32(const void* p) {
    uint32_t a;
    asm("{ .reg .u64 t; cvta.to.shared.u64 t, %1; cvt.u32.u64 %0, t; }"
        : "=r"(a) : "l"(p));
    return a;
}
__device__ __forceinline__ void cp16(uint32_t dst, const void* src) {
    asm volatile("cp.async.cg.shared.global [%0], [%1], 16;" :: "r"(dst), "l"(src));
}
__device__ __forceinline__ void cp_commit() {
    asm volatile("cp.async.commit_group;" ::: "memory");
}
template<int N>
__device__ __forceinline__ void cp_wait() {
    asm volatile("cp.async.wait_group %0;" :: "n"(N) : "memory");
}

// ---------------- fp32 -> bf16 hi/lo converter ---------------------------------
__global__ __launch_bounds__(256)
void cvt_kernel(const float* __restrict__ in, __nv_bfloat16* __restrict__ hi,
                __nv_bfloat16* __restrict__ lo, int n4) {
    for (int i = blockIdx.x * 256 + threadIdx.x; i < n4; i += gridDim.x * 256) {
        float4 v = *(const float4*)&in[i * 4];
        float4 rem;
        uint2 h = cvt_hi(v, &rem);
        *(uint2*)&hi[i * 4] = h;
        *(uint2*)&lo[i * 4] = cvt_lo(rem);
    }
}

// ============================================================================
// bf16 hi/lo HMMA GEMM, cp.async 2-stage, 2 CTAs/SM, ldmatrix fragments
// ============================================================================
#define BM 128
#define BN 128
#define KC 32
#define PWW 20                         // SMEM row pitch in words (80 B)
#define TILEW (128 * PWW)              // words per tile (10240 B)
#define STGW  (4 * TILEW)              // words per stage (Ah,Al,Bh,Bl) 40960 B
#define GSMEM_BYTES (2 * STGW * 4)     // 81920

template<bool SILU>
__global__ __launch_bounds__(256, 2)
void hmma_gemm_cp(const __nv_bfloat16* __restrict__ Ahg, const __nv_bfloat16* __restrict__ Alg,
                  const __nv_bfloat16* __restrict__ Bhg, const __nv_bfloat16* __restrict__ Blg,
                  const float* __restrict__ bias, float* __restrict__ C,
                  int N, int K) {
    extern __shared__ __align__(16) uint32_t sw[];
    const uint32_t smb = smem_u32(sw);
    const int tid  = threadIdx.x;
    const int wid  = tid >> 5;
    const int lane = tid & 31;
    const int g = lane >> 2, t = lane & 3;
    const int m0 = blockIdx.y * BM;
    const int n0 = blockIdx.x * BN;
    const int wm = (wid >> 2) * 64;
    const int wn = (wid & 3) * 32;

    // ldmatrix lane address components
    const int li = lane >> 3, lr = lane & 7;
    const int a_row = (li & 1) * 8 + lr;       // A: blocks {m0-7,k0-7},{m8-15,k0-7},{m0-7,k8-15},{m8-15,k8-15}
    const int a_wrd = (li >> 1) * 4;
    const int b_row = (li >> 1) * 8 + lr;      // B: blocks {n0-7,k0-7},{n0-7,k8-15},{n8-15,k0-7},{n8-15,k8-15}
    const int b_wrd = (li & 1) * 4;

    const __nv_bfloat16* tp[4] = {Ahg, Alg, Bhg, Blg};

    float acc[4][4][4];
    #pragma unroll
    for (int i = 0; i < 4; i++)
        #pragma unroll
        for (int j = 0; j < 4; j++)
            #pragma unroll
            for (int e = 0; e < 4; e++) acc[i][j][e] = 0.f;

    const int nc = K / KC;

    auto issue_chunk = [&](int c) {
        const int k0 = c * KC;
        const uint32_t stg_b = smb + (c & 1) * (STGW * 4);
        #pragma unroll
        for (int it = 0; it < 8; it++) {
            int idx = it * 256 + tid;
            int tile = idx >> 9;
            int r = (idx >> 2) & 127;
            int q = idx & 3;
            int row = (tile < 2 ? m0 : n0) + r;
            const __nv_bfloat16* src = tp[tile] + (size_t)row * K + k0 + q * 8;
            cp16(stg_b + tile * (TILEW * 4) + r * 80 + q * 16, src);
        }
        cp_commit();
    };

    issue_chunk(0);

    for (int c = 0; c < nc; c++) {
        cp_wait<0>();
        __syncthreads();
        if (c + 1 < nc) issue_chunk(c + 1);   // overlaps with compute below

        const uint32_t stg = smb + (c & 1) * (STGW * 4);
        const uint32_t AhB = stg;
        const uint32_t AlB = stg +     TILEW * 4;
        const uint32_t BhB = stg + 2 * TILEW * 4;
        const uint32_t BlB = stg + 3 * TILEW * 4;

        #pragma unroll
        for (int ks = 0; ks < 2; ks++) {
            uint32_t ah[4][4], al[4][4], bh[4][4], bl[4][4];
            #pragma unroll
            for (int mi = 0; mi < 4; mi++) {
                const uint32_t ao = ((wm + mi * 16 + a_row) * PWW + ks * 8 + a_wrd) * 4;
                ldm_x4(ah[mi], AhB + ao);
                ldm_x4(al[mi], AlB + ao);
            }
            #pragma unroll
            for (int njp = 0; njp < 2; njp++) {
                const uint32_t bo = ((wn + njp * 16 + b_row) * PWW + ks * 8 + b_wrd) * 4;
                ldm_x4(bh[njp], BhB + bo);
                ldm_x4(bl[njp], BlB + bo);
            }
            #pragma unroll
            for (int mi = 0; mi < 4; mi++)
                #pragma unroll
                for (int nj = 0; nj < 4; nj++) {
                    const uint32_t* bhp = &bh[nj >> 1][(nj & 1) * 2];
                    const uint32_t* blp = &bl[nj >> 1][(nj & 1) * 2];
                    mma_bf16(acc[mi][nj], ah[mi], bhp);
                    mma_bf16(acc[mi][nj], ah[mi], blp);
                    mma_bf16(acc[mi][nj], al[mi], bhp);
                }
        }
    }

    #pragma unroll
    for (int mi = 0; mi < 4; mi++) {
        const int r0 = m0 + wm + mi * 16 + g;
        #pragma unroll
        for (int nj = 0; nj < 4; nj++) {
            const int cc = n0 + wn + nj * 8 + 2 * t;
            const float b0 = bias[cc], b1 = bias[cc + 1];
            float v0 = acc[mi][nj][0] + b0;
            float v1 = acc[mi][nj][1] + b1;
            float v2 = acc[mi][nj][2] + b0;
            float v3 = acc[mi][nj][3] + b1;
            if (SILU) {
                v0 = silu_f(v0); v1 = silu_f(v1);
                v2 = silu_f(v2); v3 = silu_f(v3);
            }
            *(float2*)&C[(size_t)r0 * N + cc]       = make_float2(v0, v1);
            *(float2*)&C[(size_t)(r0 + 8) * N + cc] = make_float2(v2, v3);
        }
    }
}

// ============================================================================
// HMMA flash attention, causal-balanced: CTA processes q-tile pair (p, 15-p)
// ============================================================================
#define AQT 128
#define AKT 64
#define APW 36
#define NQT (Ss / AQT)        // 16

#define QH_OFF 0
#define QL_OFF (128 * APW)
#define BUF_OFF (2 * 128 * APW)
#define BUF_W  (4 * 64 * APW)
#define KH_O 0
#define KL_O (64 * APW)
#define VTH_O (2 * 64 * APW)
#define VTL_O (3 * 64 * APW)
#define ASMEM_BYTES ((BUF_OFF + 2 * BUF_W) * 4)

__global__ __launch_bounds__(256)
void attn_hmma(const float* __restrict__ pos_w, float* __restrict__ y) {
    extern __shared__ __align__(16) uint32_t aw[];

    const int head = blockIdx.y;
    const int b    = blockIdx.z;
    const int tid  = threadIdx.x;
    const int wid  = tid >> 5;
    const int lane = tid & 31;
    const int g = lane >> 2, t = lane & 3;

    const size_t rs = FOURD;
    const float* ubase = g_h + (size_t)b * Ss * rs + 0*Dd + head * HDim;
    const float* qbase = g_h + (size_t)b * Ss * rs + 1*Dd + head * HDim;
    const float* kbase = g_h + (size_t)b * Ss * rs + 2*Dd + head * HDim;
    const float* vbase = g_h + (size_t)b * Ss * rs + 3*Dd + head * HDim;

    float4 pk[4], pv[4];
    auto load_kv = [&](int jt) {
        const int k0 = jt * AKT;
        #pragma unroll
        for (int it = 0; it < 4; it++) {
            int idx = it * 256 + tid;
            int r = idx >> 4, c = (idx & 15) * 4;
            pk[it] = *(const float4*)&kbase[(size_t)(k0 + r) * rs + c];
            pv[it] = *(const float4*)&vbase[(size_t)(k0 + r) * rs + c];
        }
    };
    auto store_kv = [&](int buf) {
        uint32_t* base = aw + BUF_OFF + buf * BUF_W;
        __nv_bfloat16* vth = (__nv_bfloat16*)(base + VTH_O);
        __nv_bfloat16* vtl = (__nv_bfloat16*)(base + VTL_O);
        #pragma unroll
        for (int it = 0; it < 4; it++) {
            int idx = it * 256 + tid;
            int r = idx >> 4, c = (idx & 15) * 4;
            float4 rem;
            uint2 h = cvt_hi(pk[it], &rem);
            uint32_t wo = (uint32_t)(r * APW + c / 2);
            *(uint2*)(base + KH_O + wo) = h;
            *(uint2*)(base + KL_O + wo) = cvt_lo(rem);
            float vv[4] = {pv[it].x, pv[it].y, pv[it].z, pv[it].w};
            #pragma unroll
            for (int e = 0; e < 4; e++) {
                __nv_bfloat16 hi = __float2bfloat16(vv[e]);
                __nv_bfloat16 lo = __float2bfloat16(vv[e] - __bfloat162float(hi));
                vth[(c + e) * (2*APW) + r] = hi;
                vtl[(c + e) * (2*APW) + r] = lo;
            }
        }
    };

    const uint32_t* QHp = aw + QH_OFF;
    const uint32_t* QLp = aw + QL_OFF;

    #pragma unroll 1
    for (int sel = 0; sel < 2; sel++) {
        const int qt = sel == 0 ? (int)blockIdx.x : (NQT - 1 - (int)blockIdx.x);
        const int q_cta = qt * AQT;
        const int jtmax = 2 * qt + 1;
        const int q_warp = q_cta + wid * 16;

        __syncthreads();   // previous iteration finished with SMEM

        // load Q tile (128 x 64) as bf16 hi/lo
        #pragma unroll
        for (int it = 0; it < 8; it++) {
            int idx = it * 256 + tid;
            int r = idx >> 4, c = (idx & 15) * 4;
            float4 v = *(const float4*)&qbase[(size_t)(q_cta + r) * rs + c];
            float4 rem;
            uint2 h = cvt_hi(v, &rem);
            uint32_t wo = (uint32_t)(r * APW + c / 2);
            *(uint2*)(aw + QH_OFF + wo) = h;
            *(uint2*)(aw + QL_OFF + wo) = cvt_lo(rem);
        }

        load_kv(0);
        store_kv(0);
        __syncthreads();

        float O[8][4];
        #pragma unroll
        for (int nj = 0; nj < 8; nj++)
            #pragma unroll
            for (int e = 0; e < 4; e++) O[nj][e] = 0.f;

        for (int jt = 0; jt <= jtmax; jt++) {
            if (jt < jtmax) load_kv(jt + 1);

            const uint32_t* base = aw + BUF_OFF + (jt & 1) * BUF_W;
            const uint32_t* KHp  = base + KH_O;
            const uint32_t* KLp  = base + KL_O;
            const uint32_t* VHp  = base + VTH_O;
            const uint32_t* VLp  = base + VTL_O;

            if (jt * AKT <= q_warp + 15) {
                float S[8][4];
                #pragma unroll
                for (int nj = 0; nj < 8; nj++)
                    #pragma unroll
                    for (int e = 0; e < 4; e++) S[nj][e] = 0.f;

                #pragma unroll
                for (int ks = 0; ks < 4; ks++) {
                    const int qa = (wid * 16 + g) * APW + ks * 8 + t;
                    uint32_t ah[4], al[4];
                    ah[0] = QHp[qa];           ah[1] = QHp[qa + 8*APW];
                    ah[2] = QHp[qa + 4];       ah[3] = QHp[qa + 8*APW + 4];
                    al[0] = QLp[qa];           al[1] = QLp[qa + 8*APW];
                    al[2] = QLp[qa + 4];       al[3] = QLp[qa + 8*APW + 4];
                    #pragma unroll
                    for (int nj = 0; nj < 8; nj++) {
                        const int ka = (nj * 8 + g) * APW + ks * 8 + t;
                        uint32_t bh[2], bl[2];
                        bh[0] = KHp[ka]; bh[1] = KHp[ka + 4];
                        bl[0] = KLp[ka]; bl[1] = KLp[ka + 4];
                        mma_bf16(S[nj], ah, bh);
                        mma_bf16(S[nj], ah, bl);
                        mma_bf16(S[nj], al, bh);
                    }
                }

                const int qg0 = q_warp + g;
                #pragma unroll
                for (int ks2 = 0; ks2 < 4; ks2++) {
                    uint32_t ph[4], pl[4];
                    #pragma unroll
                    for (int half = 0; half < 2; half++) {
                        const float* sc = S[2*ks2 + half];
                        const int kc = jt * AKT + (2*ks2 + half) * 8 + 2*t;
                        float p00 = silu_f(sc[0] + pos_w[Mm - 1 + kc     - qg0]);
                        float p01 = silu_f(sc[1] + pos_w[Mm - 1 + kc + 1 - qg0]);
                        float p10 = silu_f(sc[2] + pos_w[Mm - 1 + kc     - (qg0+8)]);
                        float p11 = silu_f(sc[3] + pos_w[Mm - 1 + kc + 1 - (qg0+8)]);
                        if (kc     > qg0)   p00 = 0.f;
                        if (kc + 1 > qg0)   p01 = 0.f;
                        if (kc     > qg0+8) p10 = 0.f;
                        if (kc + 1 > qg0+8) p11 = 0.f;
                        __nv_bfloat16 h00 = __float2bfloat16(p00);
                        __nv_bfloat16 h01 = __float2bfloat16(p01);
                        __nv_bfloat16 h10 = __float2bfloat16(p10);
                        __nv_bfloat16 h11 = __float2bfloat16(p11);
                        __nv_bfloat162 hp0(h00, h01), hp1(h10, h11);
                        __nv_bfloat162 lp0(__float2bfloat16(p00 - __bfloat162float(h00)),
                                           __float2bfloat16(p01 - __bfloat162float(h01)));
                        __nv_bfloat162 lp1(__float2bfloat16(p10 - __bfloat162float(h10)),
                                           __float2bfloat16(p11 - __bfloat162float(h11)));
                        ph[0 + half*2] = *(uint32_t*)&hp0;
                        ph[1 + half*2] = *(uint32_t*)&hp1;
                        pl[0 + half*2] = *(uint32_t*)&lp0;
                        pl[1 + half*2] = *(uint32_t*)&lp1;
                    }
                    #pragma unroll
                    for (int nj = 0; nj < 8; nj++) {
                        const int va = (nj * 8 + g) * APW + ks2 * 8 + t;
                        uint32_t vh[2], vl[2];
                        vh[0] = VHp[va]; vh[1] = VHp[va + 4];
                        vl[0] = VLp[va]; vl[1] = VLp[va + 4];
                        mma_bf16(O[nj], ph, vh);
                        mma_bf16(O[nj], ph, vl);
                        mma_bf16(O[nj], pl, vh);
                    }
                }
            }

            if (jt < jtmax) {
                store_kv((jt + 1) & 1);
                __syncthreads();
            }
        }

        #pragma unroll
        for (int nj = 0; nj < 8; nj++) {
            const int d = nj * 8 + 2 * t;
            #pragma unroll
            for (int half = 0; half < 2; half++) {
                const int q = q_warp + g + half * 8;
                const float2 u = *(const float2*)&ubase[(size_t)q * rs + d];
                float2 r;
                r.x = O[nj][half*2 + 0] * u.x;
                r.y = O[nj][half*2 + 1] * u.y;
                *(float2*)&y[((size_t)b * Ss + q) * Dd + head * HDim + d] = r;
            }
        }
    }
}

// ---------------- LayerNorm (fp32 or bf16-hi/lo output) ------------------------
__device__ __forceinline__ float block_sum(float v, float* sbuf) {
    #pragma unroll
    for (int o = 16; o > 0; o >>= 1) v += __shfl_down_sync(0xffffffffu, v, o);
    const int lane = threadIdx.x & 31, w = threadIdx.x >> 5;
    if (lane == 0) sbuf[w] = v;
    __syncthreads();
    if (w == 0) {
        v = (lane < 8) ? sbuf[lane] : 0.f;
        #pragma unroll
        for (int o = 4; o > 0; o >>= 1) v += __shfl_down_sync(0xffffffffu, v, o);
        if (lane == 0) sbuf[0] = v;
    }
    __syncthreads();
    float r = sbuf[0];
    __syncthreads();
    return r;
}

template<bool BF16OUT>
__global__ __launch_bounds__(256)
void ln_kernel(const float* __restrict__ in, const float* __restrict__ res,
               const float* __restrict__ g, const float* __restrict__ beta,
               float* __restrict__ out,
               __nv_bfloat16* __restrict__ outh, __nv_bfloat16* __restrict__ outl) {
    __shared__ float sbuf[8];
    const size_t row = blockIdx.x;
    const int c = threadIdx.x * 4;
    float4 v = *(const float4*)&in[row * Dd + c];
    if (res) {
        float4 r = *(const float4*)&res[row * Dd + c];
        v.x += r.x; v.y += r.y; v.z += r.z; v.w += r.w;
    }
    const float total = block_sum(v.x + v.y + v.z + v.w, sbuf);
    const float mu = total * (1.f / Dd);
    float dx = v.x - mu, dy = v.y - mu, dz = v.z - mu, dw = v.w - mu;
    const float ssq = block_sum(dx*dx + dy*dy + dz*dz + dw*dw, sbuf);
    const float inv = rsqrtf(ssq * (1.f / Dd) + EPS);
    float4 gv = *(const float4*)&g[c];
    float4 bv = *(const float4*)&beta[c];
    float4 r;
    r.x = dx * inv * gv.x + bv.x;
    r.y = dy * inv * gv.y + bv.y;
    r.z = dz * inv * gv.z + bv.z;
    r.w = dw * inv * gv.w + bv.w;
    if (BF16OUT) {
        float4 rem;
        uint2 h = cvt_hi(r, &rem);
        *(uint2*)&outh[row * Dd + c] = h;
        *(uint2*)&outl[row * Dd + c] = cvt_lo(rem);
    } else {
        *(float4*)&out[row * Dd + c] = r;
    }
}

// ---------------- launch ------------------------------------------------------
extern "C" void kernel_launch(void* const* d_in, const int* in_sizes, int n_in,
                              void* d_out, int out_size) {
    const float* x     = (const float*)d_in[0];
    const float* w1    = (const float*)d_in[2];
    const float* b1    = (const float*)d_in[3];
    const float* w2    = (const float*)d_in[4];
    const float* b2    = (const float*)d_in[5];
    const float* g1    = (const float*)d_in[6];
    const float* beta1 = (const float*)d_in[7];
    const float* g2    = (const float*)d_in[8];
    const float* beta2 = (const float*)d_in[9];
    const float* pos_w = (const float*)d_in[10];
    float* out = (float*)d_out;

    float *hbuf, *ybuf, *tbuf;
    __nv_bfloat16 *xh, *xl, *w1h, *w1l, *w2h, *w2l, *zh, *zl;
    cudaGetSymbolAddress((void**)&hbuf, g_h);
    cudaGetSymbolAddress((void**)&ybuf, g_y);
    cudaGetSymbolAddress((void**)&tbuf, g_t);
    cudaGetSymbolAddress((void**)&xh,  g_xh);  cudaGetSymbolAddress((void**)&xl,  g_xl);
    cudaGetSymbolAddress((void**)&w1h, g_w1h); cudaGetSymbolAddress((void**)&w1l, g_w1l);
    cudaGetSymbolAddress((void**)&w2h, g_w2h); cudaGetSymbolAddress((void**)&w2l, g_w2l);
    cudaGetSymbolAddress((void**)&zh,  g_zh);  cudaGetSymbolAddress((void**)&zl,  g_zl);

    cudaFuncSetAttribute(hmma_gemm_cp<true>,  cudaFuncAttributeMaxDynamicSharedMemorySize, GSMEM_BYTES);
    cudaFuncSetAttribute(hmma_gemm_cp<false>, cudaFuncAttributeMaxDynamicSharedMemorySize, GSMEM_BYTES);
    cudaFuncSetAttribute(attn_hmma, cudaFuncAttributeMaxDynamicSharedMemorySize, ASMEM_BYTES);

    // 0) pre-convert x, w1, w2 to bf16 hi/lo
    cvt_kernel<<<1024, 256>>>(x,  xh,  xl,  NTOK  * Dd / 4);
    cvt_kernel<<<1024, 256>>>(w1, w1h, w1l, FOURD * Dd / 4);
    cvt_kernel<<<1024, 256>>>(w2, w2h, w2l, Dd    * Dd / 4);

    // 1) h = silu(x @ w1^T + b1)
    hmma_gemm_cp<true><<<dim3(FOURD/BN, NTOK/BM), 256, GSMEM_BYTES>>>(
        xh, xl, w1h, w1l, b1, hbuf, FOURD, Dd);

    // 2) fused HMMA attention + u gate -> g_y  (paired q-tiles for balance)
    attn_hmma<<<dim3(NQT/2, Hh, Bb), 256, ASMEM_BYTES>>>(pos_w, ybuf);

    // 3) LN1 -> z (bf16 hi/lo)
    ln_kernel<true><<<NTOK, 256>>>(ybuf, nullptr, g1, beta1, nullptr, zh, zl);

    // 4) t = z @ w2^T + b2
    hmma_gemm_cp<false><<<dim3(Dd/BN, NTOK/BM), 256, GSMEM_BYTES>>>(
        zh, zl, w2h, w2l, b2, tbuf, Dd, Dd);

    // 5) out = LN(t + x)
    ln_kernel<false><<<NTOK, 256>>>(tbuf, x, g2, beta2, out, nullptr, nullptr);
}

// round 8
// speedup vs baseline: 2.6592x; 1.2497x over previous
#include <cuda_runtime.h>
#include <cuda_bf16.h>
#include <cstdint>
#include <cstddef>

// Problem constants
#define Bb 2
#define Ss 2048
#define Dd 1024
#define Hh 16
#define HDim 64
#define Mm 4096
#define NTOK (Bb*Ss)          // 4096
#define FOURD (4*Dd)          // 4096
#define EPS 1e-5f

// ---------------- scratch ----------------------------------------------------
__device__ float g_y[(size_t)NTOK * Dd];      // gated attention out
__device__ float g_t[(size_t)NTOK * Dd];      // GEMM2 out
// bf16 hi/lo pre-converted operands
__device__ __nv_bfloat16 g_xh[(size_t)NTOK * Dd],  g_xl[(size_t)NTOK * Dd];
__device__ __nv_bfloat16 g_w1h[(size_t)FOURD * Dd], g_w1l[(size_t)FOURD * Dd];
__device__ __nv_bfloat16 g_w2h[(size_t)Dd * Dd],   g_w2l[(size_t)Dd * Dd];
__device__ __nv_bfloat16 g_zh[(size_t)NTOK * Dd],  g_zl[(size_t)NTOK * Dd];
// h = silu(x@w1^T+b1) as bf16 hi/lo (written by GEMM1 epilogue)
__device__ __nv_bfloat16 g_hh[(size_t)NTOK * FOURD], g_hl[(size_t)NTOK * FOURD];

// ---------------- common helpers ----------------------------------------------
__device__ __forceinline__ void mma_bf16(float* c, const uint32_t* a, const uint32_t* b) {
    asm volatile(
        "mma.sync.aligned.m16n8k16.row.col.f32.bf16.bf16.f32 "
        "{%0,%1,%2,%3}, {%4,%5,%6,%7}, {%8,%9}, {%0,%1,%2,%3};"
        : "+f"(c[0]), "+f"(c[1]), "+f"(c[2]), "+f"(c[3])
        : "r"(a[0]), "r"(a[1]), "r"(a[2]), "r"(a[3]), "r"(b[0]), "r"(b[1]));
}
__device__ __forceinline__ void ldm_x4(uint32_t* r, uint32_t addr) {
    asm volatile("ldmatrix.sync.aligned.m8n8.x4.shared.b16 {%0,%1,%2,%3}, [%4];"
        : "=r"(r[0]), "=r"(r[1]), "=r"(r[2]), "=r"(r[3]) : "r"(addr));
}
__device__ __forceinline__ void ldm_x4t(uint32_t* r, uint32_t addr) {
    asm volatile("ldmatrix.sync.aligned.m8n8.x4.trans.shared.b16 {%0,%1,%2,%3}, [%4];"
        : "=r"(r[0]), "=r"(r[1]), "=r"(r[2]), "=r"(r[3]) : "r"(addr));
}
__device__ __forceinline__ uint2 cvt_hi(float4 g, float4* rem) {
    __nv_bfloat16 h0 = __float2bfloat16(g.x), h1 = __float2bfloat16(g.y);
    __nv_bfloat16 h2 = __float2bfloat16(g.z), h3 = __float2bfloat16(g.w);
    rem->x = g.x - __bfloat162float(h0);
    rem->y = g.y - __bfloat162float(h1);
    rem->z = g.z - __bfloat162float(h2);
    rem->w = g.w - __bfloat162float(h3);
    __nv_bfloat162 p0(h0, h1), p1(h2, h3);
    return make_uint2(*(uint32_t*)&p0, *(uint32_t*)&p1);
}
__device__ __forceinline__ uint2 cvt_lo(float4 g) {
    __nv_bfloat16 l0 = __float2bfloat16(g.x), l1 = __float2bfloat16(g.y);
    __nv_bfloat16 l2 = __float2bfloat16(g.z), l3 = __float2bfloat16(g.w);
    __nv_bfloat162 p0(l0, l1), p1(l2, l3);
    return make_uint2(*(uint32_t*)&p0, *(uint32_t*)&p1);
}
__device__ __forceinline__ uint32_t pack_hi2(float a, float b, uint32_t* lo) {
    __nv_bfloat16 ha = __float2bfloat16(a), hb = __float2bfloat16(b);
    __nv_bfloat162 l(__float2bfloat16(a - __bfloat162float(ha)),
                     __float2bfloat16(b - __bfloat162float(hb)));
    *lo = *(uint32_t*)&l;
    __nv_bfloat162 h(ha, hb);
    return *(uint32_t*)&h;
}
__device__ __forceinline__ float silu_f(float v) {
    return v / (1.f + __expf(-v));
}
__device__ __forceinline__ uint32_t smem_u32(const void* p) {
    uint32_t a;
    asm("{ .reg .u64 t; cvta.to.shared.u64 t, %1; cvt.u32.u64 %0, t; }"
        : "=r"(a) : "l"(p));
    return a;
}
__device__ __forceinline__ void cp16(uint32_t dst, const void* src) {
    asm volatile("cp.async.cg.shared.global [%0], [%1], 16;" :: "r"(dst), "l"(src));
}
__device__ __forceinline__ void cp_commit() {
    asm volatile("cp.async.commit_group;" ::: "memory");
}
template<int N>
__device__ __forceinline__ void cp_wait() {
    asm volatile("cp.async.wait_group %0;" :: "n"(N) : "memory");
}

// ---------------- fp32 -> bf16 hi/lo converter ---------------------------------
__global__ __launch_bounds__(256)
void cvt_kernel(const float* __restrict__ in, __nv_bfloat16* __restrict__ hi,
                __nv_bfloat16* __restrict__ lo, int n4) {
    for (int i = blockIdx.x * 256 + threadIdx.x; i < n4; i += gridDim.x * 256) {
        float4 v = *(const float4*)&in[i * 4];
        float4 rem;
        uint2 h = cvt_hi(v, &rem);
        *(uint2*)&hi[i * 4] = h;
        *(uint2*)&lo[i * 4] = cvt_lo(rem);
    }
}

// ============================================================================
// bf16 hi/lo HMMA GEMM, cp.async 2-stage, 2 CTAs/SM, ldmatrix fragments
// OBF16: epilogue emits bf16 hi/lo instead of fp32
// ============================================================================
#define BM 128
#define BN 128
#define KC 32
#define PWW 20                         // SMEM row pitch in words (80 B)
#define TILEW (128 * PWW)              // words per tile (10240 B)
#define STGW  (4 * TILEW)              // words per stage 40960 B
#define GSMEM_BYTES (2 * STGW * 4)     // 81920

template<bool SILU, bool OBF16>
__global__ __launch_bounds__(256, 2)
void hmma_gemm_cp(const __nv_bfloat16* __restrict__ Ahg, const __nv_bfloat16* __restrict__ Alg,
                  const __nv_bfloat16* __restrict__ Bhg, const __nv_bfloat16* __restrict__ Blg,
                  const float* __restrict__ bias, float* __restrict__ C,
                  __nv_bfloat16* __restrict__ Ch, __nv_bfloat16* __restrict__ Cl,
                  int N, int K) {
    extern __shared__ __align__(16) uint32_t sw[];
    const uint32_t smb = smem_u32(sw);
    const int tid  = threadIdx.x;
    const int wid  = tid >> 5;
    const int lane = tid & 31;
    const int g = lane >> 2, t = lane & 3;
    const int m0 = blockIdx.y * BM;
    const int n0 = blockIdx.x * BN;
    const int wm = (wid >> 2) * 64;
    const int wn = (wid & 3) * 32;

    const int li = lane >> 3, lr = lane & 7;
    const int a_row = (li & 1) * 8 + lr;
    const int a_wrd = (li >> 1) * 4;
    const int b_row = (li >> 1) * 8 + lr;
    const int b_wrd = (li & 1) * 4;

    const __nv_bfloat16* tp[4] = {Ahg, Alg, Bhg, Blg};

    float acc[4][4][4];
    #pragma unroll
    for (int i = 0; i < 4; i++)
        #pragma unroll
        for (int j = 0; j < 4; j++)
            #pragma unroll
            for (int e = 0; e < 4; e++) acc[i][j][e] = 0.f;

    const int nc = K / KC;

    auto issue_chunk = [&](int c) {
        const int k0 = c * KC;
        const uint32_t stg_b = smb + (c & 1) * (STGW * 4);
        #pragma unroll
        for (int it = 0; it < 8; it++) {
            int idx = it * 256 + tid;
            int tile = idx >> 9;
            int r = (idx >> 2) & 127;
            int q = idx & 3;
            int row = (tile < 2 ? m0 : n0) + r;
            const __nv_bfloat16* src = tp[tile] + (size_t)row * K + k0 + q * 8;
            cp16(stg_b + tile * (TILEW * 4) + r * 80 + q * 16, src);
        }
        cp_commit();
    };

    issue_chunk(0);

    for (int c = 0; c < nc; c++) {
        cp_wait<0>();
        __syncthreads();
        if (c + 1 < nc) issue_chunk(c + 1);

        const uint32_t stg = smb + (c & 1) * (STGW * 4);
        const uint32_t AhB = stg;
        const uint32_t AlB = stg +     TILEW * 4;
        const uint32_t BhB = stg + 2 * TILEW * 4;
        const uint32_t BlB = stg + 3 * TILEW * 4;

        #pragma unroll
        for (int ks = 0; ks < 2; ks++) {
            uint32_t ah[4][4], al[4][4], bh[2][4], bl[2][4];
            #pragma unroll
            for (int mi = 0; mi < 4; mi++) {
                const uint32_t ao = ((wm + mi * 16 + a_row) * PWW + ks * 8 + a_wrd) * 4;
                ldm_x4(ah[mi], AhB + ao);
                ldm_x4(al[mi], AlB + ao);
            }
            #pragma unroll
            for (int njp = 0; njp < 2; njp++) {
                const uint32_t bo = ((wn + njp * 16 + b_row) * PWW + ks * 8 + b_wrd) * 4;
                ldm_x4(bh[njp], BhB + bo);
                ldm_x4(bl[njp], BlB + bo);
            }
            #pragma unroll
            for (int mi = 0; mi < 4; mi++)
                #pragma unroll
                for (int nj = 0; nj < 4; nj++) {
                    const uint32_t* bhp = &bh[nj >> 1][(nj & 1) * 2];
                    const uint32_t* blp = &bl[nj >> 1][(nj & 1) * 2];
                    mma_bf16(acc[mi][nj], ah[mi], bhp);
                    mma_bf16(acc[mi][nj], ah[mi], blp);
                    mma_bf16(acc[mi][nj], al[mi], bhp);
                }
        }
    }

    #pragma unroll
    for (int mi = 0; mi < 4; mi++) {
        const int r0 = m0 + wm + mi * 16 + g;
        #pragma unroll
        for (int nj = 0; nj < 4; nj++) {
            const int cc = n0 + wn + nj * 8 + 2 * t;
            const float b0 = bias[cc], b1 = bias[cc + 1];
            float v0 = acc[mi][nj][0] + b0;
            float v1 = acc[mi][nj][1] + b1;
            float v2 = acc[mi][nj][2] + b0;
            float v3 = acc[mi][nj][3] + b1;
            if (SILU) {
                v0 = silu_f(v0); v1 = silu_f(v1);
                v2 = silu_f(v2); v3 = silu_f(v3);
            }
            if (OBF16) {
                uint32_t lo0, lo1;
                uint32_t hi0 = pack_hi2(v0, v1, &lo0);
                uint32_t hi1 = pack_hi2(v2, v3, &lo1);
                *(uint32_t*)&Ch[(size_t)r0 * N + cc]       = hi0;
                *(uint32_t*)&Cl[(size_t)r0 * N + cc]       = lo0;
                *(uint32_t*)&Ch[(size_t)(r0 + 8) * N + cc] = hi1;
                *(uint32_t*)&Cl[(size_t)(r0 + 8) * N + cc] = lo1;
            } else {
                *(float2*)&C[(size_t)r0 * N + cc]       = make_float2(v0, v1);
                *(float2*)&C[(size_t)(r0 + 8) * N + cc] = make_float2(v2, v3);
            }
        }
    }
}

// ============================================================================
// HMMA flash attention v2: cp.async bf16 tiles, ldmatrix (+trans for V),
// 2 CTAs/SM, causal-balanced paired q-tiles.
// ============================================================================
#define AQT 128
#define AKT 64
#define APW 36                 // words per 64-bf16 row (144 B)
#define NQT (Ss / AQT)         // 16

#define QH_OFF 0
#define QL_OFF (128 * APW)             // 4608 words
#define BUF_OFF (2 * 128 * APW)        // 9216 words
#define TILE_KV (64 * APW)             // 2304 words
#define BUF_W (4 * TILE_KV)            // 9216 words: Kh,Kl,Vh,Vl
#define ASMEM_BYTES ((BUF_OFF + 2 * BUF_W) * 4)   // 110592 B

__global__ __launch_bounds__(256, 2)
void attn_hmma(const float* __restrict__ pos_w, float* __restrict__ y,
               const __nv_bfloat16* __restrict__ hh, const __nv_bfloat16* __restrict__ hl) {
    extern __shared__ __align__(16) uint32_t aw[];
    const uint32_t smb = smem_u32(aw);

    const int head = blockIdx.y;
    const int b    = blockIdx.z;
    const int tid  = threadIdx.x;
    const int wid  = tid >> 5;
    const int lane = tid & 31;
    const int g = lane >> 2, t = lane & 3;
    const int li = lane >> 3, lr = lane & 7;
    const int a_row = (li & 1) * 8 + lr;
    const int a_wrd = (li >> 1) * 4;
    const int b_row = (li >> 1) * 8 + lr;
    const int b_wrd = (li & 1) * 4;

    const __nv_bfloat16* hh_b = hh + (size_t)b * Ss * FOURD + head * HDim;
    const __nv_bfloat16* hl_b = hl + (size_t)b * Ss * FOURD + head * HDim;

    auto issue_q = [&](int q_cta) {
        #pragma unroll
        for (int it = 0; it < 8; it++) {
            int idx = it * 256 + tid;          // 0..2047
            int part = idx >> 10;              // 0: hi, 1: lo
            int r = (idx >> 3) & 127;
            int q8 = idx & 7;
            const __nv_bfloat16* src =
                (part ? hl_b : hh_b) + (size_t)(q_cta + r) * FOURD + 1024 + q8 * 8;
            cp16(smb + ((part ? QL_OFF : QH_OFF) + r * APW + q8 * 4) * 4, src);
        }
    };
    auto issue_kv = [&](int jt, int buf) {
        const int k0 = jt * AKT;
        const uint32_t base = BUF_OFF + buf * BUF_W;
        #pragma unroll
        for (int it = 0; it < 8; it++) {
            int idx = it * 256 + tid;          // 0..2047
            int part = idx >> 9;               // 0:Kh 1:Kl 2:Vh 3:Vl
            int r = (idx >> 3) & 63;
            int q8 = idx & 7;
            const __nv_bfloat16* bg = (part & 1) ? hl_b : hh_b;
            const int quarter = (part >> 1) ? 3072 : 2048;
            const __nv_bfloat16* src = bg + (size_t)(k0 + r) * FOURD + quarter + q8 * 8;
            cp16(smb + (base + part * TILE_KV + r * APW + q8 * 4) * 4, src);
        }
        cp_commit();
    };

    #pragma unroll 1
    for (int sel = 0; sel < 2; sel++) {
        const int qt = sel == 0 ? (int)blockIdx.x : (NQT - 1 - (int)blockIdx.x);
        const int q_cta = qt * AQT;
        const int jtmax = 2 * qt + 1;
        const int q_warp = q_cta + wid * 16;

        __syncthreads();   // all warps done with SMEM from previous sel
        issue_q(q_cta);
        issue_kv(0, 0);    // commits q+kv together

        float O[8][4];
        #pragma unroll
        for (int nj = 0; nj < 8; nj++)
            #pragma unroll
            for (int e = 0; e < 4; e++) O[nj][e] = 0.f;

        for (int jt = 0; jt <= jtmax; jt++) {
            cp_wait<0>();
            __syncthreads();
            if (jt < jtmax) issue_kv(jt + 1, (jt + 1) & 1);

            const uint32_t bufb = smb + (BUF_OFF + (jt & 1) * BUF_W) * 4;
            const uint32_t khB = bufb;
            const uint32_t klB = bufb + TILE_KV * 4;
            const uint32_t vhB = bufb + 2 * TILE_KV * 4;
            const uint32_t vlB = bufb + 3 * TILE_KV * 4;

            if (jt * AKT <= q_warp + 15) {
                // ---- S = Q @ K^T ----
                float S[8][4];
                #pragma unroll
                for (int nj = 0; nj < 8; nj++)
                    #pragma unroll
                    for (int e = 0; e < 4; e++) S[nj][e] = 0.f;

                #pragma unroll
                for (int ks = 0; ks < 4; ks++) {
                    uint32_t ah[4], al[4];
                    const uint32_t qoff = ((wid * 16 + a_row) * APW + ks * 8 + a_wrd) * 4;
                    ldm_x4(ah, smb + QH_OFF * 4 + qoff);
                    ldm_x4(al, smb + QL_OFF * 4 + qoff);
                    #pragma unroll
                    for (int nj2 = 0; nj2 < 4; nj2++) {
                        uint32_t bh4[4], bl4[4];
                        const uint32_t koff = ((nj2 * 16 + b_row) * APW + ks * 8 + b_wrd) * 4;
                        ldm_x4(bh4, khB + koff);
                        ldm_x4(bl4, klB + koff);
                        mma_bf16(S[2*nj2],   ah, bh4);
                        mma_bf16(S[2*nj2],   ah, bl4);
                        mma_bf16(S[2*nj2],   al, bh4);
                        mma_bf16(S[2*nj2+1], ah, bh4 + 2);
                        mma_bf16(S[2*nj2+1], ah, bl4 + 2);
                        mma_bf16(S[2*nj2+1], al, bh4 + 2);
                    }
                }

                // ---- P = mask(silu(S + bias)); O += P @ V ----
                const int qg0 = q_warp + g;
                #pragma unroll
                for (int ks2 = 0; ks2 < 4; ks2++) {
                    uint32_t ph[4], pl[4];
                    #pragma unroll
                    for (int half = 0; half < 2; half++) {
                        const float* sc = S[2*ks2 + half];
                        const int kc = jt * AKT + (2*ks2 + half) * 8 + 2*t;
                        float p00 = silu_f(sc[0] + pos_w[Mm - 1 + kc     - qg0]);
                        float p01 = silu_f(sc[1] + pos_w[Mm - 1 + kc + 1 - qg0]);
                        float p10 = silu_f(sc[2] + pos_w[Mm - 1 + kc     - (qg0+8)]);
                        float p11 = silu_f(sc[3] + pos_w[Mm - 1 + kc + 1 - (qg0+8)]);
                        if (kc     > qg0)   p00 = 0.f;
                        if (kc + 1 > qg0)   p01 = 0.f;
                        if (kc     > qg0+8) p10 = 0.f;
                        if (kc + 1 > qg0+8) p11 = 0.f;
                        ph[0 + half*2] = pack_hi2(p00, p01, &pl[0 + half*2]);
                        ph[1 + half*2] = pack_hi2(p10, p11, &pl[1 + half*2]);
                    }
                    #pragma unroll
                    for (int nj2 = 0; nj2 < 4; nj2++) {
                        uint32_t vh4[4], vl4[4];
                        const uint32_t voff =
                            ((ks2 * 16 + (li & 1) * 8 + lr) * APW + nj2 * 8 + (li >> 1) * 4) * 4;
                        ldm_x4t(vh4, vhB + voff);
                        ldm_x4t(vl4, vlB + voff);
                        mma_bf16(O[2*nj2],   ph, vh4);
                        mma_bf16(O[2*nj2],   ph, vl4);
                        mma_bf16(O[2*nj2],   pl, vh4);
                        mma_bf16(O[2*nj2+1], ph, vh4 + 2);
                        mma_bf16(O[2*nj2+1], ph, vl4 + 2);
                        mma_bf16(O[2*nj2+1], pl, vh4 + 2);
                    }
                }
            }
        }

        // ---- epilogue: gate by u = uh + ul, store to y [B,S,D] ----
        #pragma unroll
        for (int nj = 0; nj < 8; nj++) {
            const int d = nj * 8 + 2 * t;
            #pragma unroll
            for (int half = 0; half < 2; half++) {
                const int q = q_warp + g + half * 8;
                const uint32_t uhp = *(const uint32_t*)&hh_b[(size_t)q * FOURD + d];
                const uint32_t ulp = *(const uint32_t*)&hl_b[(size_t)q * FOURD + d];
                const __nv_bfloat162 uh2 = *(const __nv_bfloat162*)&uhp;
                const __nv_bfloat162 ul2 = *(const __nv_bfloat162*)&ulp;
                float2 r;
                r.x = O[nj][half*2 + 0] * (__bfloat162float(uh2.x) + __bfloat162float(ul2.x));
                r.y = O[nj][half*2 + 1] * (__bfloat162float(uh2.y) + __bfloat162float(ul2.y));
                *(float2*)&y[((size_t)b * Ss + q) * Dd + head * HDim + d] = r;
            }
        }
    }
}

// ---------------- LayerNorm (fp32 or bf16-hi/lo output) ------------------------
__device__ __forceinline__ float block_sum(float v, float* sbuf) {
    #pragma unroll
    for (int o = 16; o > 0; o >>= 1) v += __shfl_down_sync(0xffffffffu, v, o);
    const int lane = threadIdx.x & 31, w = threadIdx.x >> 5;
    if (lane == 0) sbuf[w] = v;
    __syncthreads();
    if (w == 0) {
        v = (lane < 8) ? sbuf[lane] : 0.f;
        #pragma unroll
        for (int o = 4; o > 0; o >>= 1) v += __shfl_down_sync(0xffffffffu, v, o);
        if (lane == 0) sbuf[0] = v;
    }
    __syncthreads();
    float r = sbuf[0];
    __syncthreads();
    return r;
}

template<bool BF16OUT>
__global__ __launch_bounds__(256)
void ln_kernel(const float* __restrict__ in, const float* __restrict__ res,
               const float* __restrict__ g, const float* __restrict__ beta,
               float* __restrict__ out,
               __nv_bfloat16* __restrict__ outh, __nv_bfloat16* __restrict__ outl) {
    __shared__ float sbuf[8];
    const size_t row = blockIdx.x;
    const int c = threadIdx.x * 4;
    float4 v = *(const float4*)&in[row * Dd + c];
    if (res) {
        float4 r = *(const float4*)&res[row * Dd + c];
        v.x += r.x; v.y += r.y; v.z += r.z; v.w += r.w;
    }
    const float total = block_sum(v.x + v.y + v.z + v.w, sbuf);
    const float mu = total * (1.f / Dd);
    float dx = v.x - mu, dy = v.y - mu, dz = v.z - mu, dw = v.w - mu;
    const float ssq = block_sum(dx*dx + dy*dy + dz*dz + dw*dw, sbuf);
    const float inv = rsqrtf(ssq * (1.f / Dd) + EPS);
    float4 gv = *(const float4*)&g[c];
    float4 bv = *(const float4*)&beta[c];
    float4 r;
    r.x = dx * inv * gv.x + bv.x;
    r.y = dy * inv * gv.y + bv.y;
    r.z = dz * inv * gv.z + bv.z;
    r.w = dw * inv * gv.w + bv.w;
    if (BF16OUT) {
        float4 rem;
        uint2 h = cvt_hi(r, &rem);
        *(uint2*)&outh[row * Dd + c] = h;
        *(uint2*)&outl[row * Dd + c] = cvt_lo(rem);
    } else {
        *(float4*)&out[row * Dd + c] = r;
    }
}

// ---------------- launch ------------------------------------------------------
extern "C" void kernel_launch(void* const* d_in, const int* in_sizes, int n_in,
                              void* d_out, int out_size) {
    const float* x     = (const float*)d_in[0];
    const float* w1    = (const float*)d_in[2];
    const float* b1    = (const float*)d_in[3];
    const float* w2    = (const float*)d_in[4];
    const float* b2    = (const float*)d_in[5];
    const float* g1    = (const float*)d_in[6];
    const float* beta1 = (const float*)d_in[7];
    const float* g2    = (const float*)d_in[8];
    const float* beta2 = (const float*)d_in[9];
    const float* pos_w = (const float*)d_in[10];
    float* out = (float*)d_out;

    float *ybuf, *tbuf;
    __nv_bfloat16 *xh, *xl, *w1h, *w1l, *w2h, *w2l, *zh, *zl, *hhp, *hlp;
    cudaGetSymbolAddress((void**)&ybuf, g_y);
    cudaGetSymbolAddress((void**)&tbuf, g_t);
    cudaGetSymbolAddress((void**)&xh,  g_xh);  cudaGetSymbolAddress((void**)&xl,  g_xl);
    cudaGetSymbolAddress((void**)&w1h, g_w1h); cudaGetSymbolAddress((void**)&w1l, g_w1l);
    cudaGetSymbolAddress((void**)&w2h, g_w2h); cudaGetSymbolAddress((void**)&w2l, g_w2l);
    cudaGetSymbolAddress((void**)&zh,  g_zh);  cudaGetSymbolAddress((void**)&zl,  g_zl);
    cudaGetSymbolAddress((void**)&hhp, g_hh);  cudaGetSymbolAddress((void**)&hlp, g_hl);

    cudaFuncSetAttribute((const void*)hmma_gemm_cp<true,true>,
                         cudaFuncAttributeMaxDynamicSharedMemorySize, GSMEM_BYTES);
    cudaFuncSetAttribute((const void*)hmma_gemm_cp<false,false>,
                         cudaFuncAttributeMaxDynamicSharedMemorySize, GSMEM_BYTES);
    cudaFuncSetAttribute((const void*)attn_hmma,
                         cudaFuncAttributeMaxDynamicSharedMemorySize, ASMEM_BYTES);

    // 0) pre-convert x, w1, w2 to bf16 hi/lo
    cvt_kernel<<<1024, 256>>>(x,  xh,  xl,  NTOK  * Dd / 4);
    cvt_kernel<<<1024, 256>>>(w1, w1h, w1l, FOURD * Dd / 4);
    cvt_kernel<<<1024, 256>>>(w2, w2h, w2l, Dd    * Dd / 4);

    // 1) h = silu(x @ w1^T + b1) -> bf16 hi/lo
    hmma_gemm_cp<true,true><<<dim3(FOURD/BN, NTOK/BM), 256, GSMEM_BYTES>>>(
        xh, xl, w1h, w1l, b1, nullptr, hhp, hlp, FOURD, Dd);

    // 2) fused HMMA attention + u gate -> g_y
    attn_hmma<<<dim3(NQT/2, Hh, Bb), 256, ASMEM_BYTES>>>(pos_w, ybuf, hhp, hlp);

    // 3) LN1 -> z (bf16 hi/lo)
    ln_kernel<true><<<NTOK, 256>>>(ybuf, nullptr, g1, beta1, nullptr, zh, zl);

    // 4) t = z @ w2^T + b2 (fp32 out)
    hmma_gemm_cp<false,false><<<dim3(Dd/BN, NTOK/BM), 256, GSMEM_BYTES>>>(
        zh, zl, w2h, w2l, b2, tbuf, nullptr, nullptr, Dd, Dd);

    // 5) out = LN(t + x)
    ln_kernel<false><<<NTOK, 256>>>(tbuf, x, g2, beta2, out, nullptr, nullptr);
}